// round 2
// baseline (speedup 1.0000x reference)
#include <cuda_runtime.h>
#include <cuda_bf16.h>
#include <cstdint>
#include <cstddef>

#define NBAT 128
#define NTIME 256
#define NCH 512
#define HDIM 512
#define BT (NBAT*NTIME)
#define NSTEPS 32
#define NOUT 96

// ------------------------- device scratch (static, no allocation) -------------------------
__device__ float g_fp[(size_t)BT*HDIM];                         // feats_proj fp32 [bt][h]
__device__ __align__(16) __nv_bfloat16 g_A0h[(size_t)BT*NCH];   // feats^T hi  [bt][c]
__device__ __align__(16) __nv_bfloat16 g_A0l[(size_t)BT*NCH];
__device__ __align__(16) __nv_bfloat16 g_Wi2h_h[HDIM*NCH], g_Wi2h_l[HDIM*NCH];
__device__ __align__(16) __nv_bfloat16 g_Wh2h_h[HDIM*HDIM], g_Wh2h_l[HDIM*HDIM];
__device__ __align__(16) __nv_bfloat16 g_Wih_h[3*HDIM*NCH],  g_Wih_l[3*HDIM*NCH];
__device__ __align__(16) __nv_bfloat16 g_Whh_h[3*HDIM*HDIM], g_Whh_l[3*HDIM*HDIM];
__device__ __align__(16) __nv_bfloat16 g_Wgen_h[NOUT*HDIM],  g_Wgen_l[NOUT*HDIM];
__device__ float g_h[NBAT*HDIM];
__device__ __align__(16) __nv_bfloat16 g_h_h[NBAT*HDIM], g_h_l[NBAT*HDIM];
__device__ float g_hp[NBAT*HDIM];
__device__ float g_e[NBAT*NTIME];
__device__ __align__(16) __nv_bfloat16 g_ctx_h[NBAT*NCH], g_ctx_l[NBAT*NCH];
__device__ float g_gi[NBAT*3*HDIM];
__device__ float g_gh[NBAT*3*HDIM];
__device__ __align__(16) __nv_bfloat16 g_hid_h[(size_t)NBAT*NSTEPS*HDIM];
__device__ __align__(16) __nv_bfloat16 g_hid_l[(size_t)NBAT*NSTEPS*HDIM];

// ------------------------- helpers -------------------------
__device__ __forceinline__ void mma16816(float* c,
    uint32_t a0, uint32_t a1, uint32_t a2, uint32_t a3, uint32_t b0, uint32_t b1)
{
    asm volatile(
        "mma.sync.aligned.m16n8k16.row.col.f32.bf16.bf16.f32 "
        "{%0,%1,%2,%3}, {%4,%5,%6,%7}, {%8,%9}, {%0,%1,%2,%3};\n"
        : "+f"(c[0]), "+f"(c[1]), "+f"(c[2]), "+f"(c[3])
        : "r"(a0), "r"(a1), "r"(a2), "r"(a3), "r"(b0), "r"(b1));
}

__device__ __forceinline__ void split_val(float v, __nv_bfloat16& hi, __nv_bfloat16& lo)
{
    hi = __float2bfloat16_rn(v);
    lo = __float2bfloat16_rn(v - __bfloat162float(hi));
}

__device__ __forceinline__ float warp_sum(float v)
{
    #pragma unroll
    for (int o = 16; o > 0; o >>= 1) v += __shfl_xor_sync(0xffffffffu, v, o);
    return v;
}

// ------------------------- split fp32 -> bf16 hi/lo -------------------------
__global__ void split_kernel(const float* __restrict__ x,
                             __nv_bfloat16* __restrict__ hi,
                             __nv_bfloat16* __restrict__ lo, int n)
{
    int i = blockIdx.x * blockDim.x + threadIdx.x;
    if (i < n) {
        __nv_bfloat16 h, l;
        split_val(x[i], h, l);
        hi[i] = h; lo[i] = l;
    }
}

// ------------------------- transpose feats [C][BT] -> A0 [BT][C] (split) -------------------------
__global__ void transpose_split_kernel(const float* __restrict__ feats)
{
    __shared__ float tile[32][33];
    int m0 = blockIdx.x * 32;   // bt
    int c0 = blockIdx.y * 32;   // channel
    int tx = threadIdx.x, ty = threadIdx.y;
    #pragma unroll
    for (int i = ty; i < 32; i += 8)
        tile[i][tx] = feats[(size_t)(c0 + i) * BT + m0 + tx];
    __syncthreads();
    #pragma unroll
    for (int i = ty; i < 32; i += 8) {
        float v = tile[tx][i];                 // feats[c0+tx][m0+i]
        size_t o = (size_t)(m0 + i) * NCH + c0 + tx;
        __nv_bfloat16 h, l;
        split_val(v, h, l);
        g_A0h[o] = h; g_A0l[o] = l;
    }
}

__global__ void zero_h_kernel()
{
    int i = blockIdx.x * 256 + threadIdx.x;
    g_h[i]   = 0.f;
    g_h_h[i] = __float2bfloat16(0.f);
    g_h_l[i] = __float2bfloat16(0.f);
}

// ------------------------- bf16x3 GEMM: C[M,N] = A[M,K] * B[N,K]^T (+bias) -------------------------
// blockIdx.z selects operand set 0 or 1 (used to fuse gi & gh GEMMs).
#define GBM 64
#define GBN 64
#define GBK 32
#define SAS 40

__global__ void __launch_bounds__(256) gemm_x3(
    const __nv_bfloat16* __restrict__ Ah,  const __nv_bfloat16* __restrict__ Al,
    const __nv_bfloat16* __restrict__ Bh,  const __nv_bfloat16* __restrict__ Bl,
    float* __restrict__ C,  const float* __restrict__ bias,
    const __nv_bfloat16* __restrict__ A2h, const __nv_bfloat16* __restrict__ A2l,
    const __nv_bfloat16* __restrict__ B2h, const __nv_bfloat16* __restrict__ B2l,
    float* __restrict__ C2, const float* __restrict__ bias2,
    int M, int N, int K)
{
    __shared__ __align__(16) __nv_bfloat16 sAh[GBM*SAS], sAl[GBM*SAS];
    __shared__ __align__(16) __nv_bfloat16 sBh[GBN*SAS], sBl[GBN*SAS];

    const int which = blockIdx.z;
    const __nv_bfloat16* pAh = which ? A2h : Ah;
    const __nv_bfloat16* pAl = which ? A2l : Al;
    const __nv_bfloat16* pBh = which ? B2h : Bh;
    const __nv_bfloat16* pBl = which ? B2l : Bl;
    float* pC = which ? C2 : C;
    const float* pb = which ? bias2 : bias;

    const int mbase = blockIdx.y * GBM;
    const int nbase = blockIdx.x * GBN;

    const int tid = threadIdx.x;
    const int warp = tid >> 5, lane = tid & 31;
    const int wm  = (warp >> 2) * 32;   // 2 warp rows x 32
    const int wn  = (warp & 3) * 16;    // 4 warp cols x 16
    const int gid = lane >> 2, tig = lane & 3;
    const int lr  = tid >> 2;           // 0..63
    const int lc  = (tid & 3) * 8;      // 0,8,16,24

    float acc[2][2][4];
    #pragma unroll
    for (int a = 0; a < 2; a++)
        #pragma unroll
        for (int b = 0; b < 2; b++)
            #pragma unroll
            for (int c = 0; c < 4; c++) acc[a][b][c] = 0.f;

    for (int kt = 0; kt < K; kt += GBK) {
        const int gk = kt + lc;
        *(uint4*)&sAh[lr*SAS + lc] = *(const uint4*)&pAh[(size_t)(mbase + lr) * K + gk];
        *(uint4*)&sAl[lr*SAS + lc] = *(const uint4*)&pAl[(size_t)(mbase + lr) * K + gk];
        const int nrow = nbase + lr;
        uint4 vh = make_uint4(0u,0u,0u,0u), vl = make_uint4(0u,0u,0u,0u);
        if (nrow < N) {
            vh = *(const uint4*)&pBh[(size_t)nrow * K + gk];
            vl = *(const uint4*)&pBl[(size_t)nrow * K + gk];
        }
        *(uint4*)&sBh[lr*SAS + lc] = vh;
        *(uint4*)&sBl[lr*SAS + lc] = vl;
        __syncthreads();

        #pragma unroll
        for (int kk = 0; kk < GBK; kk += 16) {
            uint32_t ah[2][4], al[2][4];
            #pragma unroll
            for (int mi = 0; mi < 2; mi++) {
                const int r = wm + mi*16 + gid;
                const int c = kk + tig*2;
                ah[mi][0] = *(const uint32_t*)&sAh[(r    )*SAS + c    ];
                ah[mi][1] = *(const uint32_t*)&sAh[(r + 8)*SAS + c    ];
                ah[mi][2] = *(const uint32_t*)&sAh[(r    )*SAS + c + 8];
                ah[mi][3] = *(const uint32_t*)&sAh[(r + 8)*SAS + c + 8];
                al[mi][0] = *(const uint32_t*)&sAl[(r    )*SAS + c    ];
                al[mi][1] = *(const uint32_t*)&sAl[(r + 8)*SAS + c    ];
                al[mi][2] = *(const uint32_t*)&sAl[(r    )*SAS + c + 8];
                al[mi][3] = *(const uint32_t*)&sAl[(r + 8)*SAS + c + 8];
            }
            #pragma unroll
            for (int ni = 0; ni < 2; ni++) {
                const int n = wn + ni*8 + gid;
                const int c = kk + tig*2;
                const uint32_t b0h = *(const uint32_t*)&sBh[n*SAS + c    ];
                const uint32_t b1h = *(const uint32_t*)&sBh[n*SAS + c + 8];
                const uint32_t b0l = *(const uint32_t*)&sBl[n*SAS + c    ];
                const uint32_t b1l = *(const uint32_t*)&sBl[n*SAS + c + 8];
                #pragma unroll
                for (int mi = 0; mi < 2; mi++) {
                    mma16816(acc[mi][ni], ah[mi][0], ah[mi][1], ah[mi][2], ah[mi][3], b0h, b1h);
                    mma16816(acc[mi][ni], ah[mi][0], ah[mi][1], ah[mi][2], ah[mi][3], b0l, b1l);
                    mma16816(acc[mi][ni], al[mi][0], al[mi][1], al[mi][2], al[mi][3], b0h, b1h);
                }
            }
        }
        __syncthreads();
    }

    #pragma unroll
    for (int mi = 0; mi < 2; mi++) {
        #pragma unroll
        for (int ni = 0; ni < 2; ni++) {
            const int r = mbase + wm + mi*16 + gid;
            const int c = nbase + wn + ni*8 + tig*2;
            float b0 = 0.f, b1 = 0.f;
            if (pb != nullptr) {
                if (c     < N) b0 = pb[c];
                if (c + 1 < N) b1 = pb[c + 1];
            }
            if (c < N) {
                pC[(size_t)(r    )*N + c] = acc[mi][ni][0] + b0;
                pC[(size_t)(r + 8)*N + c] = acc[mi][ni][2] + b0;
            }
            if (c + 1 < N) {
                pC[(size_t)(r    )*N + c + 1] = acc[mi][ni][1] + b1;
                pC[(size_t)(r + 8)*N + c + 1] = acc[mi][ni][3] + b1;
            }
        }
    }
}

// ------------------------- e[b,t] = sum_h w[h]*tanh(fp[b,t,h] + hp[b,h]) -------------------------
__global__ void __launch_bounds__(256) attn_e_kernel(const float* __restrict__ wscore)
{
    const int b  = blockIdx.x;
    const int t0 = blockIdx.y * 32;
    __shared__ __align__(16) float s_hp[HDIM];
    __shared__ __align__(16) float s_w[HDIM];

    const int tid = threadIdx.x;
    s_hp[tid]       = g_hp[b*HDIM + tid];
    s_hp[tid + 256] = g_hp[b*HDIM + tid + 256];
    s_w[tid]        = wscore[tid];
    s_w[tid + 256]  = wscore[tid + 256];
    __syncthreads();

    const int warp = tid >> 5, lane = tid & 31;
    #pragma unroll
    for (int tt = warp; tt < 32; tt += 8) {
        const int t = t0 + tt;
        const float* row = g_fp + ((size_t)b * NTIME + t) * HDIM;
        float p = 0.f;
        #pragma unroll
        for (int k = lane; k < HDIM; k += 32)
            p += s_w[k] * tanhf(row[k] + s_hp[k]);
        p = warp_sum(p);
        if (lane == 0) g_e[b*NTIME + t] = p;
    }
}

// ------------------------- softmax(e) and context = feats @ alpha (split to bf16) -------------------------
__global__ void __launch_bounds__(256) attn_ctx_kernel(const float* __restrict__ feats)
{
    const int b = blockIdx.x;
    const int tid = threadIdx.x;
    const int warp = tid >> 5, lane = tid & 31;
    __shared__ float s_alpha[NTIME];
    __shared__ float red[8];

    float v = g_e[b*NTIME + tid];
    // max
    float m = v;
    #pragma unroll
    for (int o = 16; o > 0; o >>= 1) m = fmaxf(m, __shfl_xor_sync(0xffffffffu, m, o));
    if (lane == 0) red[warp] = m;
    __syncthreads();
    if (warp == 0) {
        float x = (lane < 8) ? red[lane] : -1e30f;
        #pragma unroll
        for (int o = 4; o > 0; o >>= 1) x = fmaxf(x, __shfl_xor_sync(0xffffffffu, x, o));
        if (lane == 0) red[0] = x;
    }
    __syncthreads();
    const float mx = red[0];
    __syncthreads();
    float ex = __expf(v - mx);
    float s = warp_sum(ex);
    if (lane == 0) red[warp] = s;
    __syncthreads();
    if (warp == 0) {
        float x = (lane < 8) ? red[lane] : 0.f;
        #pragma unroll
        for (int o = 4; o > 0; o >>= 1) x += __shfl_xor_sync(0xffffffffu, x, o);
        if (lane == 0) red[0] = x;
    }
    __syncthreads();
    s_alpha[tid] = ex / red[0];
    __syncthreads();

    // context[c] = sum_t feats[c][b][t] * alpha[t]
    for (int c = warp; c < NCH; c += 8) {
        const float* f = feats + ((size_t)c * NBAT + b) * NTIME;
        float p = 0.f;
        #pragma unroll
        for (int t = lane; t < NTIME; t += 32)
            p += f[t] * s_alpha[t];
        p = warp_sum(p);
        if (lane == 0) {
            __nv_bfloat16 h, l;
            split_val(p, h, l);
            g_ctx_h[b*NCH + c] = h;
            g_ctx_l[b*NCH + c] = l;
        }
    }
}

// ------------------------- GRU gate update -------------------------
__global__ void __launch_bounds__(128) gru_update_kernel(int step)
{
    const int b = blockIdx.x;
    const int tid = threadIdx.x;
    #pragma unroll
    for (int jj = tid; jj < HDIM; jj += 128) {
        const float ir  = g_gi[b*3*HDIM + jj];
        const float iz  = g_gi[b*3*HDIM + HDIM + jj];
        const float in_ = g_gi[b*3*HDIM + 2*HDIM + jj];
        const float hr  = g_gh[b*3*HDIM + jj];
        const float hz  = g_gh[b*3*HDIM + HDIM + jj];
        const float hn  = g_gh[b*3*HDIM + 2*HDIM + jj];
        const float r = 1.f / (1.f + __expf(-(ir + hr)));
        const float z = 1.f / (1.f + __expf(-(iz + hz)));
        const float n = tanhf(in_ + r * hn);
        const float hprev = g_h[b*HDIM + jj];
        const float hnew = (1.f - z) * n + z * hprev;
        g_h[b*HDIM + jj] = hnew;
        __nv_bfloat16 hh, hl;
        split_val(hnew, hh, hl);
        g_h_h[b*HDIM + jj] = hh;
        g_h_l[b*HDIM + jj] = hl;
        const size_t o = ((size_t)(b*NSTEPS + step)) * HDIM + jj;
        g_hid_h[o] = hh;
        g_hid_l[o] = hl;
    }
}

// ------------------------- host -------------------------
template <typename T>
static T* sym(const void* s)
{
    void* p = nullptr;
    cudaGetSymbolAddress(&p, s);
    return (T*)p;
}

extern "C" void kernel_launch(void* const* d_in, const int* in_sizes, int n_in,
                              void* d_out, int out_size)
{
    const float* feats  = (const float*)d_in[0];
    const float* Wi2h   = (const float*)d_in[2];
    const float* Wh2h   = (const float*)d_in[3];
    const float* bh2h   = (const float*)d_in[4];
    const float* Wscore = (const float*)d_in[5];
    const float* Wih    = (const float*)d_in[6];
    const float* Whh    = (const float*)d_in[7];
    const float* bih    = (const float*)d_in[8];
    const float* bhh    = (const float*)d_in[9];
    const float* Wgen   = (const float*)d_in[10];
    const float* bgen   = (const float*)d_in[11];
    float* out = (float*)d_out;

    __nv_bfloat16* A0h    = sym<__nv_bfloat16>(g_A0h);
    __nv_bfloat16* A0l    = sym<__nv_bfloat16>(g_A0l);
    __nv_bfloat16* Wi2h_h = sym<__nv_bfloat16>(g_Wi2h_h);
    __nv_bfloat16* Wi2h_l = sym<__nv_bfloat16>(g_Wi2h_l);
    __nv_bfloat16* Wh2h_h = sym<__nv_bfloat16>(g_Wh2h_h);
    __nv_bfloat16* Wh2h_l = sym<__nv_bfloat16>(g_Wh2h_l);
    __nv_bfloat16* Wih_h  = sym<__nv_bfloat16>(g_Wih_h);
    __nv_bfloat16* Wih_l  = sym<__nv_bfloat16>(g_Wih_l);
    __nv_bfloat16* Whh_h  = sym<__nv_bfloat16>(g_Whh_h);
    __nv_bfloat16* Whh_l  = sym<__nv_bfloat16>(g_Whh_l);
    __nv_bfloat16* Wgen_h = sym<__nv_bfloat16>(g_Wgen_h);
    __nv_bfloat16* Wgen_l = sym<__nv_bfloat16>(g_Wgen_l);
    __nv_bfloat16* hh     = sym<__nv_bfloat16>(g_h_h);
    __nv_bfloat16* hl     = sym<__nv_bfloat16>(g_h_l);
    __nv_bfloat16* ctxh   = sym<__nv_bfloat16>(g_ctx_h);
    __nv_bfloat16* ctxl   = sym<__nv_bfloat16>(g_ctx_l);
    __nv_bfloat16* hidh   = sym<__nv_bfloat16>(g_hid_h);
    __nv_bfloat16* hidl   = sym<__nv_bfloat16>(g_hid_l);
    float* fp   = sym<float>(g_fp);
    float* hp   = sym<float>(g_hp);
    float* gi   = sym<float>(g_gi);
    float* gh   = sym<float>(g_gh);

    // ---- prologue: splits ----
    split_kernel<<<(HDIM*NCH + 255)/256, 256>>>(Wi2h, Wi2h_h, Wi2h_l, HDIM*NCH);
    split_kernel<<<(HDIM*HDIM + 255)/256, 256>>>(Wh2h, Wh2h_h, Wh2h_l, HDIM*HDIM);
    split_kernel<<<(3*HDIM*NCH + 255)/256, 256>>>(Wih, Wih_h, Wih_l, 3*HDIM*NCH);
    split_kernel<<<(3*HDIM*HDIM + 255)/256, 256>>>(Whh, Whh_h, Whh_l, 3*HDIM*HDIM);
    split_kernel<<<(NOUT*HDIM + 255)/256, 256>>>(Wgen, Wgen_h, Wgen_l, NOUT*HDIM);
    transpose_split_kernel<<<dim3(BT/32, NCH/32), dim3(32, 8)>>>(feats);
    zero_h_kernel<<<NBAT*HDIM/256, 256>>>();

    // ---- GEMM0: fp = A0 @ Wi2h^T  [BT x HDIM] ----
    gemm_x3<<<dim3(HDIM/GBN, BT/GBM, 1), 256>>>(
        A0h, A0l, Wi2h_h, Wi2h_l, fp, nullptr,
        nullptr, nullptr, nullptr, nullptr, nullptr, nullptr,
        BT, HDIM, NCH);

    // ---- decode loop ----
    for (int step = 0; step < NSTEPS; step++) {
        // hp = h @ Wh2h^T + bh2h
        gemm_x3<<<dim3(HDIM/GBN, NBAT/GBM, 1), 256>>>(
            hh, hl, Wh2h_h, Wh2h_l, hp, bh2h,
            nullptr, nullptr, nullptr, nullptr, nullptr, nullptr,
            NBAT, HDIM, HDIM);
        attn_e_kernel<<<dim3(NBAT, NTIME/32), 256>>>(Wscore);
        attn_ctx_kernel<<<NBAT, 256>>>(feats);
        // gi = ctx @ Wih^T + bih ; gh = h @ Whh^T + bhh (fused via z)
        gemm_x3<<<dim3(3*HDIM/GBN, NBAT/GBM, 2), 256>>>(
            ctxh, ctxl, Wih_h, Wih_l, gi, bih,
            hh, hl, Whh_h, Whh_l, gh, bhh,
            NBAT, 3*HDIM, HDIM);
        gru_update_kernel<<<NBAT, 128>>>(step);
    }

    // ---- generator: out = hiddens @ Wgen^T + bgen  [4096 x 96] ----
    gemm_x3<<<dim3((NOUT + GBN - 1)/GBN, (NBAT*NSTEPS)/GBM, 1), 256>>>(
        hidh, hidl, Wgen_h, Wgen_l, out, bgen,
        nullptr, nullptr, nullptr, nullptr, nullptr, nullptr,
        NBAT*NSTEPS, NOUT, HDIM);
}

// round 3
// speedup vs baseline: 1.5554x; 1.5554x over previous
#include <cuda_runtime.h>
#include <cuda_bf16.h>
#include <cuda_fp16.h>
#include <cstdint>
#include <cstddef>

#define NBAT 128
#define NTIME 256
#define NCH 512
#define HDIM 512
#define BT (NBAT*NTIME)
#define NSTEPS 32
#define NOUT 96

// ------------------------- device scratch -------------------------
__device__ __align__(16) __half g_fp16[(size_t)BT*HDIM];          // feats_proj fp16 [b][t][h]
__device__ __align__(16) __half g_f16ctx[(size_t)NBAT*NCH*NTIME]; // feats fp16 [b][c][t]
__device__ __align__(16) __nv_bfloat16 g_A0h[(size_t)BT*NCH];     // feats^T hi [bt][c]
__device__ __align__(16) __nv_bfloat16 g_A0l[(size_t)BT*NCH];
__device__ __align__(16) __nv_bfloat16 g_Wi2h_h[HDIM*NCH], g_Wi2h_l[HDIM*NCH];
__device__ __align__(16) __nv_bfloat16 g_Wh2h_h[HDIM*HDIM], g_Wh2h_l[HDIM*HDIM];
__device__ __align__(16) __nv_bfloat16 g_Wih_h[3*HDIM*NCH],  g_Wih_l[3*HDIM*NCH];
__device__ __align__(16) __nv_bfloat16 g_Whh_h[3*HDIM*HDIM], g_Whh_l[3*HDIM*HDIM];
__device__ __align__(16) __nv_bfloat16 g_Wgen_h[NOUT*HDIM],  g_Wgen_l[NOUT*HDIM];
// double-buffered hidden state
__device__ float g_hA_f[NBAT*HDIM], g_hB_f[NBAT*HDIM];
__device__ __align__(16) __nv_bfloat16 g_hA_h[NBAT*HDIM], g_hA_l[NBAT*HDIM];
__device__ __align__(16) __nv_bfloat16 g_hB_h[NBAT*HDIM], g_hB_l[NBAT*HDIM];
__device__ float g_hp[NBAT*HDIM];
__device__ __align__(16) __nv_bfloat16 g_ctx_h[NBAT*NCH], g_ctx_l[NBAT*NCH];
__device__ __align__(16) __nv_bfloat16 g_hid_h[(size_t)NBAT*NSTEPS*HDIM];
__device__ __align__(16) __nv_bfloat16 g_hid_l[(size_t)NBAT*NSTEPS*HDIM];

// ------------------------- helpers -------------------------
__device__ __forceinline__ void mma16816(float* c,
    uint32_t a0, uint32_t a1, uint32_t a2, uint32_t a3, uint32_t b0, uint32_t b1)
{
    asm volatile(
        "mma.sync.aligned.m16n8k16.row.col.f32.bf16.bf16.f32 "
        "{%0,%1,%2,%3}, {%4,%5,%6,%7}, {%8,%9}, {%0,%1,%2,%3};\n"
        : "+f"(c[0]), "+f"(c[1]), "+f"(c[2]), "+f"(c[3])
        : "r"(a0), "r"(a1), "r"(a2), "r"(a3), "r"(b0), "r"(b1));
}

__device__ __forceinline__ void split_val(float v, __nv_bfloat16& hi, __nv_bfloat16& lo)
{
    hi = __float2bfloat16_rn(v);
    lo = __float2bfloat16_rn(v - __bfloat162float(hi));
}

__device__ __forceinline__ float warp_sum(float v)
{
    #pragma unroll
    for (int o = 16; o > 0; o >>= 1) v += __shfl_xor_sync(0xffffffffu, v, o);
    return v;
}

__device__ __forceinline__ float warp_max(float v)
{
    #pragma unroll
    for (int o = 16; o > 0; o >>= 1) v = fmaxf(v, __shfl_xor_sync(0xffffffffu, v, o));
    return v;
}

__device__ __forceinline__ float tanh_ap(float x)
{
    float y;
    asm("tanh.approx.f32 %0, %1;" : "=f"(y) : "f"(x));
    return y;
}

// ------------------------- prologue kernels -------------------------
__global__ void split_kernel(const float* __restrict__ x,
                             __nv_bfloat16* __restrict__ hi,
                             __nv_bfloat16* __restrict__ lo, int n)
{
    int i = blockIdx.x * blockDim.x + threadIdx.x;
    if (i < n) {
        __nv_bfloat16 h, l;
        split_val(x[i], h, l);
        hi[i] = h; lo[i] = l;
    }
}

__global__ void transpose_split_kernel(const float* __restrict__ feats)
{
    __shared__ float tile[32][33];
    int m0 = blockIdx.x * 32;
    int c0 = blockIdx.y * 32;
    int tx = threadIdx.x, ty = threadIdx.y;
    #pragma unroll
    for (int i = ty; i < 32; i += 8)
        tile[i][tx] = feats[(size_t)(c0 + i) * BT + m0 + tx];
    __syncthreads();
    #pragma unroll
    for (int i = ty; i < 32; i += 8) {
        float v = tile[tx][i];
        size_t o = (size_t)(m0 + i) * NCH + c0 + tx;
        __nv_bfloat16 h, l;
        split_val(v, h, l);
        g_A0h[o] = h; g_A0l[o] = l;
    }
}

// feats [c][b][t] fp32 -> g_f16ctx [b][c][t] fp16
__global__ void feats16_kernel(const float* __restrict__ feats)
{
    size_t idx = (size_t)blockIdx.x * 256 + threadIdx.x;
    int t = idx & (NTIME - 1);
    int c = (idx >> 8) & (NCH - 1);
    int b = idx >> 17;
    g_f16ctx[idx] = __float2half(feats[((size_t)c * NBAT + b) * NTIME + t]);
}

__global__ void zero_h_kernel()
{
    int i = blockIdx.x * 256 + threadIdx.x;
    g_hA_f[i] = 0.f;
    g_hA_h[i] = __float2bfloat16(0.f);
    g_hA_l[i] = __float2bfloat16(0.f);
}

// ------------------------- bf16x3 GEMM: C = A @ B^T (+bias), optional fp16 out -------------------------
#define GBM 64
#define GBN 64
#define GBK 32
#define SAS 40

__global__ void __launch_bounds__(256) gemm_x3(
    const __nv_bfloat16* __restrict__ Ah,  const __nv_bfloat16* __restrict__ Al,
    const __nv_bfloat16* __restrict__ Bh,  const __nv_bfloat16* __restrict__ Bl,
    float* __restrict__ C, __half* __restrict__ C16, const float* __restrict__ bias,
    int M, int N, int K)
{
    __shared__ __align__(16) __nv_bfloat16 sAh[GBM*SAS], sAl[GBM*SAS];
    __shared__ __align__(16) __nv_bfloat16 sBh[GBN*SAS], sBl[GBN*SAS];

    const int mbase = blockIdx.y * GBM;
    const int nbase = blockIdx.x * GBN;

    const int tid = threadIdx.x;
    const int warp = tid >> 5, lane = tid & 31;
    const int wm  = (warp >> 2) * 32;
    const int wn  = (warp & 3) * 16;
    const int gid = lane >> 2, tig = lane & 3;
    const int lr  = tid >> 2;
    const int lc  = (tid & 3) * 8;

    float acc[2][2][4];
    #pragma unroll
    for (int a = 0; a < 2; a++)
        #pragma unroll
        for (int b = 0; b < 2; b++)
            #pragma unroll
            for (int c = 0; c < 4; c++) acc[a][b][c] = 0.f;

    for (int kt = 0; kt < K; kt += GBK) {
        const int gk = kt + lc;
        *(uint4*)&sAh[lr*SAS + lc] = *(const uint4*)&Ah[(size_t)(mbase + lr) * K + gk];
        *(uint4*)&sAl[lr*SAS + lc] = *(const uint4*)&Al[(size_t)(mbase + lr) * K + gk];
        const int nrow = nbase + lr;
        uint4 vh = make_uint4(0u,0u,0u,0u), vl = make_uint4(0u,0u,0u,0u);
        if (nrow < N) {
            vh = *(const uint4*)&Bh[(size_t)nrow * K + gk];
            vl = *(const uint4*)&Bl[(size_t)nrow * K + gk];
        }
        *(uint4*)&sBh[lr*SAS + lc] = vh;
        *(uint4*)&sBl[lr*SAS + lc] = vl;
        __syncthreads();

        #pragma unroll
        for (int kk = 0; kk < GBK; kk += 16) {
            uint32_t ah[2][4], al[2][4];
            #pragma unroll
            for (int mi = 0; mi < 2; mi++) {
                const int r = wm + mi*16 + gid;
                const int c = kk + tig*2;
                ah[mi][0] = *(const uint32_t*)&sAh[(r    )*SAS + c    ];
                ah[mi][1] = *(const uint32_t*)&sAh[(r + 8)*SAS + c    ];
                ah[mi][2] = *(const uint32_t*)&sAh[(r    )*SAS + c + 8];
                ah[mi][3] = *(const uint32_t*)&sAh[(r + 8)*SAS + c + 8];
                al[mi][0] = *(const uint32_t*)&sAl[(r    )*SAS + c    ];
                al[mi][1] = *(const uint32_t*)&sAl[(r + 8)*SAS + c    ];
                al[mi][2] = *(const uint32_t*)&sAl[(r    )*SAS + c + 8];
                al[mi][3] = *(const uint32_t*)&sAl[(r + 8)*SAS + c + 8];
            }
            #pragma unroll
            for (int ni = 0; ni < 2; ni++) {
                const int n = wn + ni*8 + gid;
                const int c = kk + tig*2;
                const uint32_t b0h = *(const uint32_t*)&sBh[n*SAS + c    ];
                const uint32_t b1h = *(const uint32_t*)&sBh[n*SAS + c + 8];
                const uint32_t b0l = *(const uint32_t*)&sBl[n*SAS + c    ];
                const uint32_t b1l = *(const uint32_t*)&sBl[n*SAS + c + 8];
                #pragma unroll
                for (int mi = 0; mi < 2; mi++) {
                    mma16816(acc[mi][ni], ah[mi][0], ah[mi][1], ah[mi][2], ah[mi][3], b0h, b1h);
                    mma16816(acc[mi][ni], ah[mi][0], ah[mi][1], ah[mi][2], ah[mi][3], b0l, b1l);
                    mma16816(acc[mi][ni], al[mi][0], al[mi][1], al[mi][2], al[mi][3], b0h, b1h);
                }
            }
        }
        __syncthreads();
    }

    #pragma unroll
    for (int mi = 0; mi < 2; mi++) {
        #pragma unroll
        for (int ni = 0; ni < 2; ni++) {
            const int r = mbase + wm + mi*16 + gid;
            const int c = nbase + wn + ni*8 + tig*2;
            float b0 = 0.f, b1 = 0.f;
            if (bias != nullptr) {
                if (c     < N) b0 = bias[c];
                if (c + 1 < N) b1 = bias[c + 1];
            }
            if (C16 != nullptr) {
                if (c < N) {
                    C16[(size_t)(r    )*N + c] = __float2half(acc[mi][ni][0] + b0);
                    C16[(size_t)(r + 8)*N + c] = __float2half(acc[mi][ni][2] + b0);
                }
                if (c + 1 < N) {
                    C16[(size_t)(r    )*N + c + 1] = __float2half(acc[mi][ni][1] + b1);
                    C16[(size_t)(r + 8)*N + c + 1] = __float2half(acc[mi][ni][3] + b1);
                }
            } else {
                if (c < N) {
                    C[(size_t)(r    )*N + c] = acc[mi][ni][0] + b0;
                    C[(size_t)(r + 8)*N + c] = acc[mi][ni][2] + b0;
                }
                if (c + 1 < N) {
                    C[(size_t)(r    )*N + c + 1] = acc[mi][ni][1] + b1;
                    C[(size_t)(r + 8)*N + c + 1] = acc[mi][ni][3] + b1;
                }
            }
        }
    }
}

// ------------------------- fused attention: e -> softmax -> context, one block per batch -------------------------
__global__ void __launch_bounds__(512) attn_fused(const float* __restrict__ wscore)
{
    const int b = blockIdx.x;
    __shared__ __align__(16) float s_hp[HDIM];
    __shared__ __align__(16) float s_w[HDIM];
    __shared__ float s_e[NTIME];
    __shared__ float red[16];

    const int tid = threadIdx.x;
    const int warp = tid >> 5, lane = tid & 31;

    for (int i = tid; i < HDIM; i += 512) {
        s_hp[i] = g_hp[b*HDIM + i];
        s_w[i]  = wscore[i];
    }
    __syncthreads();

    // ---- e[t] = sum_h w[h] * tanh(fp16[b][t][h] + hp[h]) ----
    #pragma unroll
    for (int it = 0; it < 16; it++) {
        const int t = warp + (it << 4);
        const __half2* row = (const __half2*)(g_fp16 + ((size_t)b * NTIME + t) * HDIM);
        float p = 0.f;
        #pragma unroll
        for (int j = 0; j < 8; j++) {
            const int k = lane + (j << 5);
            float2 x = __half22float2(row[k]);
            float xa = tanh_ap(x.x + s_hp[2*k]);
            float xb = tanh_ap(x.y + s_hp[2*k + 1]);
            p = fmaf(s_w[2*k], xa, p);
            p = fmaf(s_w[2*k + 1], xb, p);
        }
        p = warp_sum(p);
        if (lane == 0) s_e[t] = p;
    }
    __syncthreads();

    // ---- softmax over s_e[0..255] ----
    float v = (tid < NTIME) ? s_e[tid] : -1e30f;
    float m = warp_max(v);
    if (lane == 0) red[warp] = m;
    __syncthreads();
    if (warp == 0) {
        float x = (lane < 16) ? red[lane] : -1e30f;
        x = warp_max(x);
        if (lane == 0) red[0] = x;
    }
    __syncthreads();
    const float mx = red[0];
    __syncthreads();
    float ex = (tid < NTIME) ? __expf(v - mx) : 0.f;
    float s = warp_sum(ex);
    if (lane == 0) red[warp] = s;
    __syncthreads();
    if (warp == 0) {
        float x = (lane < 16) ? red[lane] : 0.f;
        x = warp_sum(x);
        if (lane == 0) red[0] = x;
    }
    __syncthreads();
    const float inv = 1.f / red[0];
    if (tid < NTIME) s_e[tid] = ex * inv;
    __syncthreads();

    // ---- context[c] = sum_t feats16[b][c][t] * alpha[t] ----
    #pragma unroll
    for (int ic = 0; ic < 32; ic++) {
        const int c = warp + (ic << 4);
        const __half2* row = (const __half2*)(g_f16ctx + ((size_t)b * NCH + c) * NTIME);
        float p = 0.f;
        #pragma unroll
        for (int j = 0; j < 4; j++) {
            const int k = lane + (j << 5);
            float2 f = __half22float2(row[k]);
            p = fmaf(f.x, s_e[2*k], p);
            p = fmaf(f.y, s_e[2*k + 1], p);
        }
        p = warp_sum(p);
        if (lane == 0) {
            __nv_bfloat16 h, l;
            split_val(p, h, l);
            g_ctx_h[b*NCH + c] = h;
            g_ctx_l[b*NCH + c] = l;
        }
    }
}

// ------------------------- fused gi/gh GEMM + GRU update -------------------------
// grid (HDIM/16, NBAT/64) = (32, 2); 256 threads.
#define GGN 16

__global__ void __launch_bounds__(256) gemm_gru(
    const __nv_bfloat16* __restrict__ hin_h, const __nv_bfloat16* __restrict__ hin_l,
    const float* __restrict__ hin_f,
    __nv_bfloat16* __restrict__ hout_h, __nv_bfloat16* __restrict__ hout_l,
    float* __restrict__ hout_f,
    const float* __restrict__ bih, const float* __restrict__ bhh,
    int step)
{
    __shared__ __align__(16) __nv_bfloat16 sA[4][GBM*SAS];   // ctx_h, ctx_l, h_h, h_l
    __shared__ __align__(16) __nv_bfloat16 sB[12][GGN*SAS];  // 6 gate strips x (hi,lo)

    const int nbase = blockIdx.x * GGN;
    const int mbase = blockIdx.y * GBM;
    const int tid = threadIdx.x;
    const int warp = tid >> 5, lane = tid & 31;
    const int wm = (warp >> 1) * 16;
    const int wn = (warp & 1) * 8;
    const int gid = lane >> 2, tig = lane & 3;

    float acc[6][4];
    #pragma unroll
    for (int g = 0; g < 6; g++)
        #pragma unroll
        for (int i = 0; i < 4; i++) acc[g][i] = 0.f;

    const __nv_bfloat16* aptr[4] = { g_ctx_h, g_ctx_l, hin_h, hin_l };

    for (int kt = 0; kt < HDIM; kt += GBK) {
        // loader: A = 4 sets x 64 rows, B = 12 sets x 16 rows; 16B chunks, 4 per row
        #pragma unroll
        for (int i = tid; i < 1792; i += 256) {
            const int chunk = i & 3;
            const int rowid = i >> 2;
            const __nv_bfloat16* src;
            __nv_bfloat16* dst;
            if (rowid < 256) {
                const int set = rowid >> 6, r = rowid & 63;
                src = aptr[set] + (size_t)(mbase + r) * HDIM + kt + chunk*8;
                dst = &sA[set][r*SAS + chunk*8];
            } else {
                const int rb = rowid - 256;
                const int set = rb >> 4, r = rb & 15;
                const int gate = set >> 1, hl = set & 1;
                const __nv_bfloat16* base = (gate < 3) ? (hl ? g_Wih_l : g_Wih_h)
                                                       : (hl ? g_Whh_l : g_Whh_h);
                const int grow = ((gate < 3) ? gate : (gate - 3)) * HDIM + nbase + r;
                src = base + (size_t)grow * HDIM + kt + chunk*8;
                dst = &sB[set][r*SAS + chunk*8];
            }
            *(uint4*)dst = *(const uint4*)src;
        }
        __syncthreads();

        #pragma unroll
        for (int kk = 0; kk < GBK; kk += 16) {
            const int cc = kk + tig*2;
            const int r0 = wm + gid;
            uint32_t ac_h[4], ac_l[4], ah_h[4], ah_l[4];
            ac_h[0] = *(const uint32_t*)&sA[0][(r0    )*SAS + cc    ];
            ac_h[1] = *(const uint32_t*)&sA[0][(r0 + 8)*SAS + cc    ];
            ac_h[2] = *(const uint32_t*)&sA[0][(r0    )*SAS + cc + 8];
            ac_h[3] = *(const uint32_t*)&sA[0][(r0 + 8)*SAS + cc + 8];
            ac_l[0] = *(const uint32_t*)&sA[1][(r0    )*SAS + cc    ];
            ac_l[1] = *(const uint32_t*)&sA[1][(r0 + 8)*SAS + cc    ];
            ac_l[2] = *(const uint32_t*)&sA[1][(r0    )*SAS + cc + 8];
            ac_l[3] = *(const uint32_t*)&sA[1][(r0 + 8)*SAS + cc + 8];
            ah_h[0] = *(const uint32_t*)&sA[2][(r0    )*SAS + cc    ];
            ah_h[1] = *(const uint32_t*)&sA[2][(r0 + 8)*SAS + cc    ];
            ah_h[2] = *(const uint32_t*)&sA[2][(r0    )*SAS + cc + 8];
            ah_h[3] = *(const uint32_t*)&sA[2][(r0 + 8)*SAS + cc + 8];
            ah_l[0] = *(const uint32_t*)&sA[3][(r0    )*SAS + cc    ];
            ah_l[1] = *(const uint32_t*)&sA[3][(r0 + 8)*SAS + cc    ];
            ah_l[2] = *(const uint32_t*)&sA[3][(r0    )*SAS + cc + 8];
            ah_l[3] = *(const uint32_t*)&sA[3][(r0 + 8)*SAS + cc + 8];
            #pragma unroll
            for (int g = 0; g < 6; g++) {
                const int br = wn + gid;
                const uint32_t b0h = *(const uint32_t*)&sB[2*g  ][br*SAS + cc    ];
                const uint32_t b1h = *(const uint32_t*)&sB[2*g  ][br*SAS + cc + 8];
                const uint32_t b0l = *(const uint32_t*)&sB[2*g+1][br*SAS + cc    ];
                const uint32_t b1l = *(const uint32_t*)&sB[2*g+1][br*SAS + cc + 8];
                const uint32_t* Ah_ = (g < 3) ? ac_h : ah_h;
                const uint32_t* Al_ = (g < 3) ? ac_l : ah_l;
                mma16816(acc[g], Ah_[0], Ah_[1], Ah_[2], Ah_[3], b0h, b1h);
                mma16816(acc[g], Ah_[0], Ah_[1], Ah_[2], Ah_[3], b0l, b1l);
                mma16816(acc[g], Al_[0], Al_[1], Al_[2], Al_[3], b0h, b1h);
            }
        }
        __syncthreads();
    }

    // ---- GRU epilogue ----
    const int row0 = mbase + wm + gid;
    const int j0 = nbase + wn + tig*2;
    #pragma unroll
    for (int mi = 0; mi < 2; mi++) {
        const int row = row0 + mi*8;
        #pragma unroll
        for (int ji = 0; ji < 2; ji++) {
            const int j = j0 + ji;
            const int ai = mi*2 + ji;
            const float ir  = acc[0][ai] + bih[j];
            const float iz  = acc[1][ai] + bih[HDIM + j];
            const float in_ = acc[2][ai] + bih[2*HDIM + j];
            const float hr  = acc[3][ai] + bhh[j];
            const float hz  = acc[4][ai] + bhh[HDIM + j];
            const float hn  = acc[5][ai] + bhh[2*HDIM + j];
            const float r = 1.f / (1.f + __expf(-(ir + hr)));
            const float z = 1.f / (1.f + __expf(-(iz + hz)));
            const float n = tanhf(in_ + r * hn);
            const float hprev = hin_f[row*HDIM + j];
            const float hnew = (1.f - z) * n + z * hprev;
            hout_f[row*HDIM + j] = hnew;
            __nv_bfloat16 hh, hl;
            split_val(hnew, hh, hl);
            hout_h[row*HDIM + j] = hh;
            hout_l[row*HDIM + j] = hl;
            const size_t o = ((size_t)(row*NSTEPS + step)) * HDIM + j;
            g_hid_h[o] = hh;
            g_hid_l[o] = hl;
        }
    }
}

// ------------------------- host -------------------------
template <typename T>
static T* sym(const void* s)
{
    void* p = nullptr;
    cudaGetSymbolAddress(&p, s);
    return (T*)p;
}

extern "C" void kernel_launch(void* const* d_in, const int* in_sizes, int n_in,
                              void* d_out, int out_size)
{
    const float* feats  = (const float*)d_in[0];
    const float* Wi2h   = (const float*)d_in[2];
    const float* Wh2h   = (const float*)d_in[3];
    const float* bh2h   = (const float*)d_in[4];
    const float* Wscore = (const float*)d_in[5];
    const float* Wih    = (const float*)d_in[6];
    const float* Whh    = (const float*)d_in[7];
    const float* bih    = (const float*)d_in[8];
    const float* bhh    = (const float*)d_in[9];
    const float* Wgen   = (const float*)d_in[10];
    const float* bgen   = (const float*)d_in[11];
    float* out = (float*)d_out;

    __nv_bfloat16* A0h    = sym<__nv_bfloat16>(g_A0h);
    __nv_bfloat16* A0l    = sym<__nv_bfloat16>(g_A0l);
    __nv_bfloat16* Wi2h_h = sym<__nv_bfloat16>(g_Wi2h_h);
    __nv_bfloat16* Wi2h_l = sym<__nv_bfloat16>(g_Wi2h_l);
    __nv_bfloat16* Wh2h_h = sym<__nv_bfloat16>(g_Wh2h_h);
    __nv_bfloat16* Wh2h_l = sym<__nv_bfloat16>(g_Wh2h_l);
    __nv_bfloat16* Wih_h  = sym<__nv_bfloat16>(g_Wih_h);
    __nv_bfloat16* Wih_l  = sym<__nv_bfloat16>(g_Wih_l);
    __nv_bfloat16* Whh_h  = sym<__nv_bfloat16>(g_Whh_h);
    __nv_bfloat16* Whh_l  = sym<__nv_bfloat16>(g_Whh_l);
    __nv_bfloat16* Wgen_h = sym<__nv_bfloat16>(g_Wgen_h);
    __nv_bfloat16* Wgen_l = sym<__nv_bfloat16>(g_Wgen_l);
    __nv_bfloat16* hidh   = sym<__nv_bfloat16>(g_hid_h);
    __nv_bfloat16* hidl   = sym<__nv_bfloat16>(g_hid_l);
    __half* fp16 = sym<__half>(g_fp16);
    float*  hp   = sym<float>(g_hp);

    __nv_bfloat16* hbh[2] = { sym<__nv_bfloat16>(g_hA_h), sym<__nv_bfloat16>(g_hB_h) };
    __nv_bfloat16* hbl[2] = { sym<__nv_bfloat16>(g_hA_l), sym<__nv_bfloat16>(g_hB_l) };
    float*         hbf[2] = { sym<float>(g_hA_f), sym<float>(g_hB_f) };

    // ---- prologue ----
    split_kernel<<<(HDIM*NCH + 255)/256, 256>>>(Wi2h, Wi2h_h, Wi2h_l, HDIM*NCH);
    split_kernel<<<(HDIM*HDIM + 255)/256, 256>>>(Wh2h, Wh2h_h, Wh2h_l, HDIM*HDIM);
    split_kernel<<<(3*HDIM*NCH + 255)/256, 256>>>(Wih, Wih_h, Wih_l, 3*HDIM*NCH);
    split_kernel<<<(3*HDIM*HDIM + 255)/256, 256>>>(Whh, Whh_h, Whh_l, 3*HDIM*HDIM);
    split_kernel<<<(NOUT*HDIM + 255)/256, 256>>>(Wgen, Wgen_h, Wgen_l, NOUT*HDIM);
    transpose_split_kernel<<<dim3(BT/32, NCH/32), dim3(32, 8)>>>(feats);
    feats16_kernel<<<(int)(((size_t)NBAT*NCH*NTIME)/256), 256>>>(feats);
    zero_h_kernel<<<NBAT*HDIM/256, 256>>>();

    // ---- GEMM0: feats_proj (fp16 out) ----
    gemm_x3<<<dim3(HDIM/GBN, BT/GBM), 256>>>(
        A0h, A0l, Wi2h_h, Wi2h_l, nullptr, fp16, nullptr, BT, HDIM, NCH);

    // ---- decode loop: 3 kernels per step ----
    int cur = 0;
    for (int step = 0; step < NSTEPS; step++) {
        const int nxt = cur ^ 1;
        gemm_x3<<<dim3(HDIM/GBN, NBAT/GBM), 256>>>(
            hbh[cur], hbl[cur], Wh2h_h, Wh2h_l, hp, nullptr, bh2h, NBAT, HDIM, HDIM);
        attn_fused<<<NBAT, 512>>>(Wscore);
        gemm_gru<<<dim3(HDIM/GGN, NBAT/GBM), 256>>>(
            hbh[cur], hbl[cur], hbf[cur], hbh[nxt], hbl[nxt], hbf[nxt], bih, bhh, step);
        cur = nxt;
    }

    // ---- generator ----
    gemm_x3<<<dim3((NOUT + GBN - 1)/GBN, (NBAT*NSTEPS)/GBM), 256>>>(
        hidh, hidl, Wgen_h, Wgen_l, out, nullptr, bgen, NBAT*NSTEPS, NOUT, HDIM);
}

// round 4
// speedup vs baseline: 1.7096x; 1.0992x over previous
#include <cuda_runtime.h>
#include <cuda_bf16.h>
#include <cuda_fp16.h>
#include <cstdint>
#include <cstddef>

#define NBAT 128
#define NTIME 256
#define NCH 512
#define HDIM 512
#define BT (NBAT*NTIME)
#define NSTEPS 32
#define NOUT 96

// ------------------------- device scratch -------------------------
__device__ __align__(16) __half g_fp16[(size_t)BT*HDIM];          // feats_proj fp16 [b][t][h]
__device__ __align__(16) __half g_f16ctx[(size_t)NBAT*NCH*NTIME]; // feats fp16 [b][c][t]
__device__ __align__(16) __half g_hp16[NBAT*HDIM];                // hp fp16 [b][h]
__device__ __align__(16) __nv_bfloat16 g_A0h[(size_t)BT*NCH];
__device__ __align__(16) __nv_bfloat16 g_A0l[(size_t)BT*NCH];
__device__ __align__(16) __nv_bfloat16 g_Wi2h_h[HDIM*NCH], g_Wi2h_l[HDIM*NCH];
__device__ __align__(16) __nv_bfloat16 g_Wh2h_h[HDIM*HDIM], g_Wh2h_l[HDIM*HDIM];
__device__ __align__(16) __nv_bfloat16 g_Wih_h[3*HDIM*NCH],  g_Wih_l[3*HDIM*NCH];
__device__ __align__(16) __nv_bfloat16 g_Whh_h[3*HDIM*HDIM], g_Whh_l[3*HDIM*HDIM];
__device__ __align__(16) __nv_bfloat16 g_Wgen_h[NOUT*HDIM],  g_Wgen_l[NOUT*HDIM];
__device__ float g_hA_f[NBAT*HDIM], g_hB_f[NBAT*HDIM];
__device__ __align__(16) __nv_bfloat16 g_hA_h[NBAT*HDIM], g_hA_l[NBAT*HDIM];
__device__ __align__(16) __nv_bfloat16 g_hB_h[NBAT*HDIM], g_hB_l[NBAT*HDIM];
__device__ __align__(16) __nv_bfloat16 g_ctx_h[NBAT*NCH], g_ctx_l[NBAT*NCH];
__device__ __align__(16) __nv_bfloat16 g_hid_h[(size_t)NBAT*NSTEPS*HDIM];
__device__ __align__(16) __nv_bfloat16 g_hid_l[(size_t)NBAT*NSTEPS*HDIM];

// ------------------------- helpers -------------------------
__device__ __forceinline__ void mma16816(float* c,
    uint32_t a0, uint32_t a1, uint32_t a2, uint32_t a3, uint32_t b0, uint32_t b1)
{
    asm volatile(
        "mma.sync.aligned.m16n8k16.row.col.f32.bf16.bf16.f32 "
        "{%0,%1,%2,%3}, {%4,%5,%6,%7}, {%8,%9}, {%0,%1,%2,%3};\n"
        : "+f"(c[0]), "+f"(c[1]), "+f"(c[2]), "+f"(c[3])
        : "r"(a0), "r"(a1), "r"(a2), "r"(a3), "r"(b0), "r"(b1));
}

__device__ __forceinline__ void split_val(float v, __nv_bfloat16& hi, __nv_bfloat16& lo)
{
    hi = __float2bfloat16_rn(v);
    lo = __float2bfloat16_rn(v - __bfloat162float(hi));
}

__device__ __forceinline__ float warp_sum(float v)
{
    #pragma unroll
    for (int o = 16; o > 0; o >>= 1) v += __shfl_xor_sync(0xffffffffu, v, o);
    return v;
}

__device__ __forceinline__ float warp_max(float v)
{
    #pragma unroll
    for (int o = 16; o > 0; o >>= 1) v = fmaxf(v, __shfl_xor_sync(0xffffffffu, v, o));
    return v;
}

__device__ __forceinline__ float tanh_ap(float x)
{
    float y;
    asm("tanh.approx.f32 %0, %1;" : "=f"(y) : "f"(x));
    return y;
}

__device__ __forceinline__ void cp16(void* d, const void* s)
{
    uint32_t ds = (uint32_t)__cvta_generic_to_shared(d);
    asm volatile("cp.async.ca.shared.global [%0], [%1], 16;\n" :: "r"(ds), "l"(s));
}
__device__ __forceinline__ void cp16z(void* d, const void* s, bool valid)
{
    uint32_t ds = (uint32_t)__cvta_generic_to_shared(d);
    int sz = valid ? 16 : 0;
    asm volatile("cp.async.ca.shared.global [%0], [%1], 16, %2;\n" :: "r"(ds), "l"(s), "r"(sz));
}
__device__ __forceinline__ void cp_commit() { asm volatile("cp.async.commit_group;\n"); }
__device__ __forceinline__ void cp_wait1()  { asm volatile("cp.async.wait_group 1;\n"); }
__device__ __forceinline__ void cp_wait0()  { asm volatile("cp.async.wait_group 0;\n"); }

// ------------------------- prologue kernels -------------------------
__global__ void fused_split(const float* __restrict__ W0, const float* __restrict__ W1,
                            const float* __restrict__ W2, const float* __restrict__ W3,
                            const float* __restrict__ W4)
{
    const int n0 = HDIM*NCH;
    const int n1 = n0 + HDIM*HDIM;
    const int n2 = n1 + 3*HDIM*NCH;
    const int n3 = n2 + 3*HDIM*HDIM;
    const int n4 = n3 + NOUT*HDIM;
    int i = blockIdx.x * 256 + threadIdx.x;
    if (i >= n4) return;
    const float* src; __nv_bfloat16 *dh, *dl; int off;
    if (i < n0)      { src = W0; dh = g_Wi2h_h; dl = g_Wi2h_l; off = i; }
    else if (i < n1) { src = W1; dh = g_Wh2h_h; dl = g_Wh2h_l; off = i - n0; }
    else if (i < n2) { src = W2; dh = g_Wih_h;  dl = g_Wih_l;  off = i - n1; }
    else if (i < n3) { src = W3; dh = g_Whh_h;  dl = g_Whh_l;  off = i - n2; }
    else             { src = W4; dh = g_Wgen_h; dl = g_Wgen_l; off = i - n3; }
    __nv_bfloat16 h, l;
    split_val(src[off], h, l);
    dh[off] = h; dl[off] = l;
}

__global__ void transpose_split_kernel(const float* __restrict__ feats)
{
    __shared__ float tile[32][33];
    int m0 = blockIdx.x * 32;
    int c0 = blockIdx.y * 32;
    int tx = threadIdx.x, ty = threadIdx.y;
    #pragma unroll
    for (int i = ty; i < 32; i += 8)
        tile[i][tx] = feats[(size_t)(c0 + i) * BT + m0 + tx];
    __syncthreads();
    #pragma unroll
    for (int i = ty; i < 32; i += 8) {
        float v = tile[tx][i];
        size_t o = (size_t)(m0 + i) * NCH + c0 + tx;
        __nv_bfloat16 h, l;
        split_val(v, h, l);
        g_A0h[o] = h; g_A0l[o] = l;
    }
}

// feats [c][b][t] -> g_f16ctx [b][c][t] fp16; also zero h
__global__ void feats16_zero_kernel(const float* __restrict__ feats)
{
    size_t idx = (size_t)blockIdx.x * 256 + threadIdx.x;
    int t = idx & (NTIME - 1);
    int c = (idx >> 8) & (NCH - 1);
    int b = (int)(idx >> 17);
    g_f16ctx[idx] = __float2half(feats[((size_t)c * NBAT + b) * NTIME + t]);
    if (idx < NBAT*HDIM) {
        g_hA_f[idx] = 0.f;
        g_hA_h[idx] = __float2bfloat16(0.f);
        g_hA_l[idx] = __float2bfloat16(0.f);
    }
}

// ------------------------- bf16x3 GEMM, 2-stage cp.async pipeline -------------------------
#define GBM 64
#define GBN 64
#define GBK 32
#define SAS 40

__global__ void __launch_bounds__(256) gemm_x3(
    const __nv_bfloat16* __restrict__ Ah,  const __nv_bfloat16* __restrict__ Al,
    const __nv_bfloat16* __restrict__ Bh,  const __nv_bfloat16* __restrict__ Bl,
    float* __restrict__ C, __half* __restrict__ C16, const float* __restrict__ bias,
    int M, int N, int K)
{
    __shared__ __align__(16) __nv_bfloat16 sAh[2][GBM*SAS], sAl[2][GBM*SAS];
    __shared__ __align__(16) __nv_bfloat16 sBh[2][GBN*SAS], sBl[2][GBN*SAS];

    const int mbase = blockIdx.y * GBM;
    const int nbase = blockIdx.x * GBN;

    const int tid = threadIdx.x;
    const int warp = tid >> 5, lane = tid & 31;
    const int wm  = (warp >> 2) * 32;
    const int wn  = (warp & 3) * 16;
    const int gid = lane >> 2, tig = lane & 3;
    const int lr  = tid >> 2;
    const int lc  = (tid & 3) * 8;

    const int nrow = nbase + lr;
    const bool nv = nrow < N;
    const int nr = nv ? nrow : 0;

    float acc[2][2][4];
    #pragma unroll
    for (int a = 0; a < 2; a++)
        #pragma unroll
        for (int b = 0; b < 2; b++)
            #pragma unroll
            for (int c = 0; c < 4; c++) acc[a][b][c] = 0.f;

    const int niter = K / GBK;

    // stage 0
    {
        const int gk = lc;
        cp16(&sAh[0][lr*SAS + lc], &Ah[(size_t)(mbase + lr) * K + gk]);
        cp16(&sAl[0][lr*SAS + lc], &Al[(size_t)(mbase + lr) * K + gk]);
        cp16z(&sBh[0][lr*SAS + lc], &Bh[(size_t)nr * K + gk], nv);
        cp16z(&sBl[0][lr*SAS + lc], &Bl[(size_t)nr * K + gk], nv);
        cp_commit();
    }

    for (int it = 0; it < niter; it++) {
        if (it + 1 < niter) {
            const int buf = (it + 1) & 1;
            const int gk = (it + 1) * GBK + lc;
            cp16(&sAh[buf][lr*SAS + lc], &Ah[(size_t)(mbase + lr) * K + gk]);
            cp16(&sAl[buf][lr*SAS + lc], &Al[(size_t)(mbase + lr) * K + gk]);
            cp16z(&sBh[buf][lr*SAS + lc], &Bh[(size_t)nr * K + gk], nv);
            cp16z(&sBl[buf][lr*SAS + lc], &Bl[(size_t)nr * K + gk], nv);
            cp_commit();
            cp_wait1();
        } else {
            cp_wait0();
        }
        __syncthreads();
        const int bf = it & 1;

        #pragma unroll
        for (int kk = 0; kk < GBK; kk += 16) {
            uint32_t ah[2][4], al[2][4];
            #pragma unroll
            for (int mi = 0; mi < 2; mi++) {
                const int r = wm + mi*16 + gid;
                const int c = kk + tig*2;
                ah[mi][0] = *(const uint32_t*)&sAh[bf][(r    )*SAS + c    ];
                ah[mi][1] = *(const uint32_t*)&sAh[bf][(r + 8)*SAS + c    ];
                ah[mi][2] = *(const uint32_t*)&sAh[bf][(r    )*SAS + c + 8];
                ah[mi][3] = *(const uint32_t*)&sAh[bf][(r + 8)*SAS + c + 8];
                al[mi][0] = *(const uint32_t*)&sAl[bf][(r    )*SAS + c    ];
                al[mi][1] = *(const uint32_t*)&sAl[bf][(r + 8)*SAS + c    ];
                al[mi][2] = *(const uint32_t*)&sAl[bf][(r    )*SAS + c + 8];
                al[mi][3] = *(const uint32_t*)&sAl[bf][(r + 8)*SAS + c + 8];
            }
            #pragma unroll
            for (int ni = 0; ni < 2; ni++) {
                const int n = wn + ni*8 + gid;
                const int c = kk + tig*2;
                const uint32_t b0h = *(const uint32_t*)&sBh[bf][n*SAS + c    ];
                const uint32_t b1h = *(const uint32_t*)&sBh[bf][n*SAS + c + 8];
                const uint32_t b0l = *(const uint32_t*)&sBl[bf][n*SAS + c    ];
                const uint32_t b1l = *(const uint32_t*)&sBl[bf][n*SAS + c + 8];
                #pragma unroll
                for (int mi = 0; mi < 2; mi++) {
                    mma16816(acc[mi][ni], ah[mi][0], ah[mi][1], ah[mi][2], ah[mi][3], b0h, b1h);
                    mma16816(acc[mi][ni], ah[mi][0], ah[mi][1], ah[mi][2], ah[mi][3], b0l, b1l);
                    mma16816(acc[mi][ni], al[mi][0], al[mi][1], al[mi][2], al[mi][3], b0h, b1h);
                }
            }
        }
        __syncthreads();
    }

    #pragma unroll
    for (int mi = 0; mi < 2; mi++) {
        #pragma unroll
        for (int ni = 0; ni < 2; ni++) {
            const int r = mbase + wm + mi*16 + gid;
            const int c = nbase + wn + ni*8 + tig*2;
            float b0 = 0.f, b1 = 0.f;
            if (bias != nullptr) {
                if (c     < N) b0 = bias[c];
                if (c + 1 < N) b1 = bias[c + 1];
            }
            if (C16 != nullptr) {
                if (c < N) {
                    C16[(size_t)(r    )*N + c] = __float2half(acc[mi][ni][0] + b0);
                    C16[(size_t)(r + 8)*N + c] = __float2half(acc[mi][ni][2] + b0);
                }
                if (c + 1 < N) {
                    C16[(size_t)(r    )*N + c + 1] = __float2half(acc[mi][ni][1] + b1);
                    C16[(size_t)(r + 8)*N + c + 1] = __float2half(acc[mi][ni][3] + b1);
                }
            } else {
                if (c < N) {
                    C[(size_t)(r    )*N + c] = acc[mi][ni][0] + b0;
                    C[(size_t)(r + 8)*N + c] = acc[mi][ni][2] + b0;
                }
                if (c + 1 < N) {
                    C[(size_t)(r    )*N + c + 1] = acc[mi][ni][1] + b1;
                    C[(size_t)(r + 8)*N + c + 1] = acc[mi][ni][3] + b1;
                }
            }
        }
    }
}

// ------------------------- fused attention -------------------------
__global__ void __launch_bounds__(512) attn_fused(const float* __restrict__ wscore)
{
    const int b = blockIdx.x;
    __shared__ __align__(16) __half2 s_hp2[HDIM/2];
    __shared__ __align__(16) float s_w[HDIM];
    __shared__ float s_e[NTIME];
    __shared__ float red[16];

    const int tid = threadIdx.x;
    const int warp = tid >> 5, lane = tid & 31;

    if (tid < 64)  ((uint4*)s_hp2)[tid] = ((const uint4*)(g_hp16 + b*HDIM))[tid];
    if (tid >= 128 && tid < 256) ((float4*)s_w)[tid - 128] = ((const float4*)wscore)[tid - 128];
    __syncthreads();

    // per-lane invariants (same for all t rows)
    uint4 hpv[2];
    float wv[16];
    #pragma unroll
    for (int jj = 0; jj < 2; jj++) {
        const int idx = lane + jj*32;
        hpv[jj] = ((const uint4*)s_hp2)[idx];
        #pragma unroll
        for (int q = 0; q < 8; q++) wv[jj*8 + q] = s_w[idx*8 + q];
    }

    // ---- e[t] ----
    #pragma unroll
    for (int it = 0; it < 16; it++) {
        const int t = warp + (it << 4);
        const uint4* row4 = (const uint4*)(g_fp16 + ((size_t)b * NTIME + t) * HDIM);
        float p = 0.f;
        #pragma unroll
        for (int jj = 0; jj < 2; jj++) {
            const uint4 v = row4[lane + jj*32];
            const __half2* vh = (const __half2*)&v;
            const __half2* hh = (const __half2*)&hpv[jj];
            #pragma unroll
            for (int q = 0; q < 4; q++) {
                float2 f = __half22float2(__hadd2(vh[q], hh[q]));
                p = fmaf(wv[jj*8 + 2*q],     tanh_ap(f.x), p);
                p = fmaf(wv[jj*8 + 2*q + 1], tanh_ap(f.y), p);
            }
        }
        p = warp_sum(p);
        if (lane == 0) s_e[t] = p;
    }
    __syncthreads();

    // ---- softmax ----
    float v = (tid < NTIME) ? s_e[tid] : -1e30f;
    float m = warp_max(v);
    if (lane == 0) red[warp] = m;
    __syncthreads();
    if (warp == 0) {
        float x = (lane < 16) ? red[lane] : -1e30f;
        x = warp_max(x);
        if (lane == 0) red[0] = x;
    }
    __syncthreads();
    const float mx = red[0];
    __syncthreads();
    float ex = (tid < NTIME) ? __expf(v - mx) : 0.f;
    float s = warp_sum(ex);
    if (lane == 0) red[warp] = s;
    __syncthreads();
    if (warp == 0) {
        float x = (lane < 16) ? red[lane] : 0.f;
        x = warp_sum(x);
        if (lane == 0) red[0] = x;
    }
    __syncthreads();
    const float inv = 1.f / red[0];
    if (tid < NTIME) s_e[tid] = ex * inv;
    __syncthreads();

    // per-lane alpha (fixed across c)
    float av[8];
    #pragma unroll
    for (int q = 0; q < 8; q++) av[q] = s_e[lane*8 + q];

    // ---- context ----
    #pragma unroll
    for (int ic = 0; ic < 32; ic++) {
        const int c = warp + (ic << 4);
        const uint4 v4 = ((const uint4*)(g_f16ctx + ((size_t)b * NCH + c) * NTIME))[lane];
        const __half2* vh = (const __half2*)&v4;
        float p = 0.f;
        #pragma unroll
        for (int q = 0; q < 4; q++) {
            float2 f = __half22float2(vh[q]);
            p = fmaf(f.x, av[2*q],     p);
            p = fmaf(f.y, av[2*q + 1], p);
        }
        p = warp_sum(p);
        if (lane == 0) {
            __nv_bfloat16 h, l;
            split_val(p, h, l);
            g_ctx_h[b*NCH + c] = h;
            g_ctx_l[b*NCH + c] = l;
        }
    }
}

// ------------------------- fused gi/gh GEMM + GRU, 2-stage cp.async, dynamic smem -------------------------
#define GGN 16
#define GRU_A_SZ (4*GBM*SAS)
#define GRU_B_SZ (12*GGN*SAS)
#define GRU_BUF (GRU_A_SZ + GRU_B_SZ)
#define GRU_SMEM_BYTES (2*GRU_BUF*2)

__global__ void __launch_bounds__(256) gemm_gru(
    const __nv_bfloat16* __restrict__ hin_h, const __nv_bfloat16* __restrict__ hin_l,
    const float* __restrict__ hin_f,
    __nv_bfloat16* __restrict__ hout_h, __nv_bfloat16* __restrict__ hout_l,
    float* __restrict__ hout_f,
    const float* __restrict__ bih, const float* __restrict__ bhh,
    int step)
{
    extern __shared__ __nv_bfloat16 dyn[];
    // layout: buf0 [A sets 0..3][B sets 0..11], buf1 same
    const int nbase = blockIdx.x * GGN;
    const int mbase = blockIdx.y * GBM;
    const int tid = threadIdx.x;
    const int warp = tid >> 5, lane = tid & 31;
    const int wm = (warp >> 1) * 16;
    const int wn = (warp & 1) * 8;
    const int gid = lane >> 2, tig = lane & 3;

    float acc[6][4];
    #pragma unroll
    for (int g = 0; g < 6; g++)
        #pragma unroll
        for (int i = 0; i < 4; i++) acc[g][i] = 0.f;

    const __nv_bfloat16* aptr[4] = { g_ctx_h, g_ctx_l, hin_h, hin_l };

    auto issue = [&](int kt, int buf) {
        __nv_bfloat16* base = dyn + buf * GRU_BUF;
        #pragma unroll
        for (int i = tid; i < 1792; i += 256) {
            const int chunk = i & 3;
            const int rowid = i >> 2;
            const __nv_bfloat16* src;
            __nv_bfloat16* dst;
            if (rowid < 256) {
                const int set = rowid >> 6, r = rowid & 63;
                src = aptr[set] + (size_t)(mbase + r) * HDIM + kt + chunk*8;
                dst = base + set*(GBM*SAS) + r*SAS + chunk*8;
            } else {
                const int rb = rowid - 256;
                const int set = rb >> 4, r = rb & 15;
                const int gate = set >> 1, hl = set & 1;
                const __nv_bfloat16* wsrc = (gate < 3) ? (hl ? g_Wih_l : g_Wih_h)
                                                       : (hl ? g_Whh_l : g_Whh_h);
                const int grow = ((gate < 3) ? gate : (gate - 3)) * HDIM + nbase + r;
                src = wsrc + (size_t)grow * HDIM + kt + chunk*8;
                dst = base + GRU_A_SZ + set*(GGN*SAS) + r*SAS + chunk*8;
            }
            cp16(dst, src);
        }
        cp_commit();
    };

    issue(0, 0);
    const int niter = HDIM / GBK;
    for (int it = 0; it < niter; it++) {
        if (it + 1 < niter) { issue((it + 1) * GBK, (it + 1) & 1); cp_wait1(); }
        else cp_wait0();
        __syncthreads();
        const __nv_bfloat16* base = dyn + (it & 1) * GRU_BUF;
        const __nv_bfloat16* sA0 = base;
        const __nv_bfloat16* sB0 = base + GRU_A_SZ;

        #pragma unroll
        for (int kk = 0; kk < GBK; kk += 16) {
            const int cc = kk + tig*2;
            const int r0 = wm + gid;
            uint32_t ac_h[4], ac_l[4], ah_h[4], ah_l[4];
            ac_h[0] = *(const uint32_t*)&sA0[0*(GBM*SAS) + (r0    )*SAS + cc    ];
            ac_h[1] = *(const uint32_t*)&sA0[0*(GBM*SAS) + (r0 + 8)*SAS + cc    ];
            ac_h[2] = *(const uint32_t*)&sA0[0*(GBM*SAS) + (r0    )*SAS + cc + 8];
            ac_h[3] = *(const uint32_t*)&sA0[0*(GBM*SAS) + (r0 + 8)*SAS + cc + 8];
            ac_l[0] = *(const uint32_t*)&sA0[1*(GBM*SAS) + (r0    )*SAS + cc    ];
            ac_l[1] = *(const uint32_t*)&sA0[1*(GBM*SAS) + (r0 + 8)*SAS + cc    ];
            ac_l[2] = *(const uint32_t*)&sA0[1*(GBM*SAS) + (r0    )*SAS + cc + 8];
            ac_l[3] = *(const uint32_t*)&sA0[1*(GBM*SAS) + (r0 + 8)*SAS + cc + 8];
            ah_h[0] = *(const uint32_t*)&sA0[2*(GBM*SAS) + (r0    )*SAS + cc    ];
            ah_h[1] = *(const uint32_t*)&sA0[2*(GBM*SAS) + (r0 + 8)*SAS + cc    ];
            ah_h[2] = *(const uint32_t*)&sA0[2*(GBM*SAS) + (r0    )*SAS + cc + 8];
            ah_h[3] = *(const uint32_t*)&sA0[2*(GBM*SAS) + (r0 + 8)*SAS + cc + 8];
            ah_l[0] = *(const uint32_t*)&sA0[3*(GBM*SAS) + (r0    )*SAS + cc    ];
            ah_l[1] = *(const uint32_t*)&sA0[3*(GBM*SAS) + (r0 + 8)*SAS + cc    ];
            ah_l[2] = *(const uint32_t*)&sA0[3*(GBM*SAS) + (r0    )*SAS + cc + 8];
            ah_l[3] = *(const uint32_t*)&sA0[3*(GBM*SAS) + (r0 + 8)*SAS + cc + 8];
            #pragma unroll
            for (int g = 0; g < 6; g++) {
                const int br = wn + gid;
                const uint32_t b0h = *(const uint32_t*)&sB0[(2*g  )*(GGN*SAS) + br*SAS + cc    ];
                const uint32_t b1h = *(const uint32_t*)&sB0[(2*g  )*(GGN*SAS) + br*SAS + cc + 8];
                const uint32_t b0l = *(const uint32_t*)&sB0[(2*g+1)*(GGN*SAS) + br*SAS + cc    ];
                const uint32_t b1l = *(const uint32_t*)&sB0[(2*g+1)*(GGN*SAS) + br*SAS + cc + 8];
                const uint32_t* Ah_ = (g < 3) ? ac_h : ah_h;
                const uint32_t* Al_ = (g < 3) ? ac_l : ah_l;
                mma16816(acc[g], Ah_[0], Ah_[1], Ah_[2], Ah_[3], b0h, b1h);
                mma16816(acc[g], Ah_[0], Ah_[1], Ah_[2], Ah_[3], b0l, b1l);
                mma16816(acc[g], Al_[0], Al_[1], Al_[2], Al_[3], b0h, b1h);
            }
        }
        __syncthreads();
    }

    // ---- GRU epilogue ----
    const int row0 = mbase + wm + gid;
    const int j0 = nbase + wn + tig*2;
    #pragma unroll
    for (int mi = 0; mi < 2; mi++) {
        const int row = row0 + mi*8;
        #pragma unroll
        for (int ji = 0; ji < 2; ji++) {
            const int j = j0 + ji;
            const int ai = mi*2 + ji;
            const float ir  = acc[0][ai] + bih[j];
            const float iz  = acc[1][ai] + bih[HDIM + j];
            const float in_ = acc[2][ai] + bih[2*HDIM + j];
            const float hr  = acc[3][ai] + bhh[j];
            const float hz  = acc[4][ai] + bhh[HDIM + j];
            const float hn  = acc[5][ai] + bhh[2*HDIM + j];
            const float r = 1.f / (1.f + __expf(-(ir + hr)));
            const float z = 1.f / (1.f + __expf(-(iz + hz)));
            const float n = tanhf(in_ + r * hn);
            const float hprev = hin_f[row*HDIM + j];
            const float hnew = (1.f - z) * n + z * hprev;
            hout_f[row*HDIM + j] = hnew;
            __nv_bfloat16 hh, hl;
            split_val(hnew, hh, hl);
            hout_h[row*HDIM + j] = hh;
            hout_l[row*HDIM + j] = hl;
            const size_t o = ((size_t)(row*NSTEPS + step)) * HDIM + j;
            g_hid_h[o] = hh;
            g_hid_l[o] = hl;
        }
    }
}

// ------------------------- host -------------------------
template <typename T>
static T* sym(const void* s)
{
    void* p = nullptr;
    cudaGetSymbolAddress(&p, s);
    return (T*)p;
}

extern "C" void kernel_launch(void* const* d_in, const int* in_sizes, int n_in,
                              void* d_out, int out_size)
{
    const float* feats  = (const float*)d_in[0];
    const float* Wi2h   = (const float*)d_in[2];
    const float* Wh2h   = (const float*)d_in[3];
    const float* bh2h   = (const float*)d_in[4];
    const float* Wscore = (const float*)d_in[5];
    const float* Wih    = (const float*)d_in[6];
    const float* Whh    = (const float*)d_in[7];
    const float* bih    = (const float*)d_in[8];
    const float* bhh    = (const float*)d_in[9];
    const float* Wgen   = (const float*)d_in[10];
    const float* bgen   = (const float*)d_in[11];
    float* out = (float*)d_out;

    __nv_bfloat16* A0h    = sym<__nv_bfloat16>(g_A0h);
    __nv_bfloat16* A0l    = sym<__nv_bfloat16>(g_A0l);
    __nv_bfloat16* Wi2h_h = sym<__nv_bfloat16>(g_Wi2h_h);
    __nv_bfloat16* Wi2h_l = sym<__nv_bfloat16>(g_Wi2h_l);
    __nv_bfloat16* Wh2h_h = sym<__nv_bfloat16>(g_Wh2h_h);
    __nv_bfloat16* Wh2h_l = sym<__nv_bfloat16>(g_Wh2h_l);
    __nv_bfloat16* Wgen_h = sym<__nv_bfloat16>(g_Wgen_h);
    __nv_bfloat16* Wgen_l = sym<__nv_bfloat16>(g_Wgen_l);
    __nv_bfloat16* hidh   = sym<__nv_bfloat16>(g_hid_h);
    __nv_bfloat16* hidl   = sym<__nv_bfloat16>(g_hid_l);
    __half* fp16 = sym<__half>(g_fp16);
    __half* hp16 = sym<__half>(g_hp16);

    __nv_bfloat16* hbh[2] = { sym<__nv_bfloat16>(g_hA_h), sym<__nv_bfloat16>(g_hB_h) };
    __nv_bfloat16* hbl[2] = { sym<__nv_bfloat16>(g_hA_l), sym<__nv_bfloat16>(g_hB_l) };
    float*         hbf[2] = { sym<float>(g_hA_f), sym<float>(g_hB_f) };

    cudaFuncSetAttribute(gemm_gru, cudaFuncAttributeMaxDynamicSharedMemorySize, GRU_SMEM_BYTES);

    // ---- prologue: 3 launches ----
    {
        const int total = HDIM*NCH + HDIM*HDIM + 3*HDIM*NCH + 3*HDIM*HDIM + NOUT*HDIM;
        fused_split<<<(total + 255)/256, 256>>>(Wi2h, Wh2h, Wih, Whh, Wgen);
    }
    transpose_split_kernel<<<dim3(BT/32, NCH/32), dim3(32, 8)>>>(feats);
    feats16_zero_kernel<<<(int)(((size_t)NBAT*NCH*NTIME)/256), 256>>>(feats);

    // ---- GEMM0 (launch 3) ----
    gemm_x3<<<dim3(HDIM/GBN, BT/GBM), 256>>>(
        A0h, A0l, Wi2h_h, Wi2h_l, nullptr, fp16, nullptr, BT, HDIM, NCH);

    // ---- decode loop: launches 4,5,6 then repeating (ncu -s 5 captures step-0 attn_fused) ----
    int cur = 0;
    for (int step = 0; step < NSTEPS; step++) {
        const int nxt = cur ^ 1;
        gemm_x3<<<dim3(HDIM/GBN, NBAT/GBM), 256>>>(
            hbh[cur], hbl[cur], Wh2h_h, Wh2h_l, nullptr, hp16, bh2h, NBAT, HDIM, HDIM);
        attn_fused<<<NBAT, 512>>>(Wscore);
        gemm_gru<<<dim3(HDIM/GGN, NBAT/GBM), 256, GRU_SMEM_BYTES>>>(
            hbh[cur], hbl[cur], hbf[cur], hbh[nxt], hbl[nxt], hbf[nxt], bih, bhh, step);
        cur = nxt;
    }

    // ---- generator ----
    gemm_x3<<<dim3((NOUT + GBN - 1)/GBN, (NBAT*NSTEPS)/GBM), 256>>>(
        hidh, hidl, Wgen_h, Wgen_l, out, nullptr, bgen, NBAT*NSTEPS, NOUT, HDIM);
}

// round 5
// speedup vs baseline: 2.0057x; 1.1732x over previous
#include <cuda_runtime.h>
#include <cuda_bf16.h>
#include <cuda_fp16.h>
#include <cstdint>
#include <cstddef>

#define NBAT 128
#define NTIME 256
#define NCH 512
#define HDIM 512
#define BT (NBAT*NTIME)
#define NSTEPS 32
#define NOUT 96

// ------------------------- device scratch -------------------------
__device__ __align__(16) __half g_fp16[(size_t)BT*HDIM];          // feats_proj fp16 [b][t][h]
__device__ __align__(16) __half g_f16ctx[(size_t)NBAT*NCH*NTIME]; // feats fp16 [b][c][t]
__device__ __align__(16) __half g_hp16[NBAT*HDIM];                // hp fp16 [b][h]
__device__ __align__(16) __half g_A0f16[(size_t)BT*NCH];          // feats^T fp16 [bt][c]
__device__ __align__(16) __half g_Wi2h16[HDIM*NCH];               // fp16 weights
__device__ __align__(16) __half g_Wh2h16[HDIM*HDIM];
__device__ __align__(16) __half g_h16[NBAT*HDIM];                 // h fp16 (for hp gemm)
__device__ __align__(16) __nv_bfloat16 g_Wih_h[3*HDIM*NCH],  g_Wih_l[3*HDIM*NCH];
__device__ __align__(16) __nv_bfloat16 g_Whh_h[3*HDIM*HDIM], g_Whh_l[3*HDIM*HDIM];
__device__ __align__(16) __nv_bfloat16 g_Wgen_h[NOUT*HDIM],  g_Wgen_l[NOUT*HDIM];
__device__ float g_hA_f[NBAT*HDIM], g_hB_f[NBAT*HDIM];
__device__ __align__(16) __nv_bfloat16 g_hA_h[NBAT*HDIM], g_hA_l[NBAT*HDIM];
__device__ __align__(16) __nv_bfloat16 g_hB_h[NBAT*HDIM], g_hB_l[NBAT*HDIM];
__device__ __align__(16) __nv_bfloat16 g_ctx_h[NBAT*NCH], g_ctx_l[NBAT*NCH];
__device__ __align__(16) __nv_bfloat16 g_hid_h[(size_t)NBAT*NSTEPS*HDIM];
__device__ __align__(16) __nv_bfloat16 g_hid_l[(size_t)NBAT*NSTEPS*HDIM];

// ------------------------- helpers -------------------------
__device__ __forceinline__ void mma16816(float* c,
    uint32_t a0, uint32_t a1, uint32_t a2, uint32_t a3, uint32_t b0, uint32_t b1)
{
    asm volatile(
        "mma.sync.aligned.m16n8k16.row.col.f32.bf16.bf16.f32 "
        "{%0,%1,%2,%3}, {%4,%5,%6,%7}, {%8,%9}, {%0,%1,%2,%3};\n"
        : "+f"(c[0]), "+f"(c[1]), "+f"(c[2]), "+f"(c[3])
        : "r"(a0), "r"(a1), "r"(a2), "r"(a3), "r"(b0), "r"(b1));
}

__device__ __forceinline__ void mma16816_f16(float* c,
    uint32_t a0, uint32_t a1, uint32_t a2, uint32_t a3, uint32_t b0, uint32_t b1)
{
    asm volatile(
        "mma.sync.aligned.m16n8k16.row.col.f32.f16.f16.f32 "
        "{%0,%1,%2,%3}, {%4,%5,%6,%7}, {%8,%9}, {%0,%1,%2,%3};\n"
        : "+f"(c[0]), "+f"(c[1]), "+f"(c[2]), "+f"(c[3])
        : "r"(a0), "r"(a1), "r"(a2), "r"(a3), "r"(b0), "r"(b1));
}

__device__ __forceinline__ void ldsm_x4(uint32_t& r0, uint32_t& r1, uint32_t& r2, uint32_t& r3,
                                        uint32_t addr)
{
    asm volatile("ldmatrix.sync.aligned.m8n8.x4.shared.b16 {%0,%1,%2,%3}, [%4];"
        : "=r"(r0), "=r"(r1), "=r"(r2), "=r"(r3) : "r"(addr));
}

__device__ __forceinline__ void split_val(float v, __nv_bfloat16& hi, __nv_bfloat16& lo)
{
    hi = __float2bfloat16_rn(v);
    lo = __float2bfloat16_rn(v - __bfloat162float(hi));
}

__device__ __forceinline__ float warp_sum(float v)
{
    #pragma unroll
    for (int o = 16; o > 0; o >>= 1) v += __shfl_xor_sync(0xffffffffu, v, o);
    return v;
}

__device__ __forceinline__ float warp_max(float v)
{
    #pragma unroll
    for (int o = 16; o > 0; o >>= 1) v = fmaxf(v, __shfl_xor_sync(0xffffffffu, v, o));
    return v;
}

__device__ __forceinline__ float tanh_ap(float x)
{
    float y;
    asm("tanh.approx.f32 %0, %1;" : "=f"(y) : "f"(x));
    return y;
}

__device__ __forceinline__ void cp16(void* d, const void* s)
{
    uint32_t ds = (uint32_t)__cvta_generic_to_shared(d);
    asm volatile("cp.async.ca.shared.global [%0], [%1], 16;\n" :: "r"(ds), "l"(s));
}
__device__ __forceinline__ void cp_commit() { asm volatile("cp.async.commit_group;\n"); }
__device__ __forceinline__ void cp_wait1()  { asm volatile("cp.async.wait_group 1;\n"); }
__device__ __forceinline__ void cp_wait0()  { asm volatile("cp.async.wait_group 0;\n"); }

// ------------------------- prologue kernels -------------------------
// Wi2h, Wh2h -> fp16; Wih, Whh, Wgen -> bf16 hi/lo
__global__ void fused_split(const float* __restrict__ W0, const float* __restrict__ W1,
                            const float* __restrict__ W2, const float* __restrict__ W3,
                            const float* __restrict__ W4)
{
    const int n0 = HDIM*NCH;
    const int n1 = n0 + HDIM*HDIM;
    const int n2 = n1 + 3*HDIM*NCH;
    const int n3 = n2 + 3*HDIM*HDIM;
    const int n4 = n3 + NOUT*HDIM;
    int i = blockIdx.x * 256 + threadIdx.x;
    if (i >= n4) return;
    if (i < n0)      { g_Wi2h16[i] = __float2half(W0[i]); return; }
    if (i < n1)      { g_Wh2h16[i - n0] = __float2half(W1[i - n0]); return; }
    const float* src; __nv_bfloat16 *dh, *dl; int off;
    if (i < n2)      { src = W2; dh = g_Wih_h;  dl = g_Wih_l;  off = i - n1; }
    else if (i < n3) { src = W3; dh = g_Whh_h;  dl = g_Whh_l;  off = i - n2; }
    else             { src = W4; dh = g_Wgen_h; dl = g_Wgen_l; off = i - n3; }
    __nv_bfloat16 h, l;
    split_val(src[off], h, l);
    dh[off] = h; dl[off] = l;
}

__global__ void transpose_kernel(const float* __restrict__ feats)
{
    __shared__ float tile[32][33];
    int m0 = blockIdx.x * 32;
    int c0 = blockIdx.y * 32;
    int tx = threadIdx.x, ty = threadIdx.y;
    #pragma unroll
    for (int i = ty; i < 32; i += 8)
        tile[i][tx] = feats[(size_t)(c0 + i) * BT + m0 + tx];
    __syncthreads();
    #pragma unroll
    for (int i = ty; i < 32; i += 8)
        g_A0f16[(size_t)(m0 + i) * NCH + c0 + tx] = __float2half(tile[tx][i]);
}

// feats [c][b][t] -> g_f16ctx [b][c][t] fp16; zero h (all representations)
__global__ void feats16_zero_kernel(const float* __restrict__ feats)
{
    size_t idx = (size_t)blockIdx.x * 256 + threadIdx.x;
    int t = idx & (NTIME - 1);
    int c = (idx >> 8) & (NCH - 1);
    int b = (int)(idx >> 17);
    g_f16ctx[idx] = __float2half(feats[((size_t)c * NBAT + b) * NTIME + t]);
    if (idx < NBAT*HDIM) {
        g_hA_f[idx] = 0.f;
        g_hA_h[idx] = __float2bfloat16(0.f);
        g_hA_l[idx] = __float2bfloat16(0.f);
        g_h16[idx]  = __float2half(0.f);
    }
}

#define SAS 40

// ------------------------- fp16 single-pass GEMM with ldmatrix -------------------------
// C16[M,N] = fp16( A[M,K] @ B[N,K]^T + bias ).  M,N multiples of 64, K multiple of 32.
#define FBM 64
#define FBN 64
#define FBK 32

__global__ void __launch_bounds__(256) gemm_f16(
    const __half* __restrict__ A, const __half* __restrict__ B,
    __half* __restrict__ C16, const float* __restrict__ bias,
    int M, int N, int K)
{
    __shared__ __align__(16) __half sA[2][FBM*SAS], sB[2][FBN*SAS];

    const int mbase = blockIdx.y * FBM;
    const int nbase = blockIdx.x * FBN;

    const int tid = threadIdx.x;
    const int warp = tid >> 5, lane = tid & 31;
    const int wm  = (warp >> 2) * 32;   // 2 warp rows x 32
    const int wn  = (warp & 3) * 16;    // 4 warp cols x 16
    const int gid = lane >> 2, tig = lane & 3;
    const int lr  = tid >> 2;           // 0..63
    const int lc  = (tid & 3) * 8;      // 0,8,16,24

    // ldmatrix source offsets (element units within an sA/sB buffer)
    const int aRow = wm + (lane & 15);
    const int aCol = (lane >> 4) * 8;
    const int bRow = wn + (lane & 7) + ((lane & 16) ? 8 : 0);
    const int bCol = (lane & 8) ? 8 : 0;

    uint32_t aBase[2], bBase[2];
    #pragma unroll
    for (int s = 0; s < 2; s++) {
        aBase[s] = (uint32_t)__cvta_generic_to_shared(&sA[s][aRow*SAS + aCol]);
        bBase[s] = (uint32_t)__cvta_generic_to_shared(&sB[s][bRow*SAS + bCol]);
    }

    float acc[2][2][4];
    #pragma unroll
    for (int a = 0; a < 2; a++)
        #pragma unroll
        for (int b = 0; b < 2; b++)
            #pragma unroll
            for (int c = 0; c < 4; c++) acc[a][b][c] = 0.f;

    const int niter = K / FBK;

    {
        cp16(&sA[0][lr*SAS + lc], &A[(size_t)(mbase + lr) * K + lc]);
        cp16(&sB[0][lr*SAS + lc], &B[(size_t)(nbase + lr) * K + lc]);
        cp_commit();
    }

    for (int it = 0; it < niter; it++) {
        if (it + 1 < niter) {
            const int buf = (it + 1) & 1;
            const int gk = (it + 1) * FBK + lc;
            cp16(&sA[buf][lr*SAS + lc], &A[(size_t)(mbase + lr) * K + gk]);
            cp16(&sB[buf][lr*SAS + lc], &B[(size_t)(nbase + lr) * K + gk]);
            cp_commit();
            cp_wait1();
        } else {
            cp_wait0();
        }
        __syncthreads();
        const int bf = it & 1;

        #pragma unroll
        for (int kk = 0; kk < FBK; kk += 16) {
            uint32_t a0[4], a1[4], b[4];
            ldsm_x4(a0[0], a0[1], a0[2], a0[3], aBase[bf] + kk*2);
            ldsm_x4(a1[0], a1[1], a1[2], a1[3], aBase[bf] + (16*SAS + kk)*2);
            ldsm_x4(b[0], b[1], b[2], b[3], bBase[bf] + kk*2);
            mma16816_f16(acc[0][0], a0[0], a0[1], a0[2], a0[3], b[0], b[1]);
            mma16816_f16(acc[0][1], a0[0], a0[1], a0[2], a0[3], b[2], b[3]);
            mma16816_f16(acc[1][0], a1[0], a1[1], a1[2], a1[3], b[0], b[1]);
            mma16816_f16(acc[1][1], a1[0], a1[1], a1[2], a1[3], b[2], b[3]);
        }
        __syncthreads();
    }

    #pragma unroll
    for (int mi = 0; mi < 2; mi++) {
        #pragma unroll
        for (int ni = 0; ni < 2; ni++) {
            const int r = mbase + wm + mi*16 + gid;
            const int c = nbase + wn + ni*8 + tig*2;
            float b0 = 0.f, b1 = 0.f;
            if (bias != nullptr) { b0 = bias[c]; b1 = bias[c + 1]; }
            C16[(size_t)(r    )*N + c    ] = __float2half(acc[mi][ni][0] + b0);
            C16[(size_t)(r    )*N + c + 1] = __float2half(acc[mi][ni][1] + b1);
            C16[(size_t)(r + 8)*N + c    ] = __float2half(acc[mi][ni][2] + b0);
            C16[(size_t)(r + 8)*N + c + 1] = __float2half(acc[mi][ni][3] + b1);
        }
    }
}

// ------------------------- bf16x3 GEMM (generator only) -------------------------
#define GBM 64
#define GBN 64
#define GBK 32

__global__ void __launch_bounds__(256) gemm_x3(
    const __nv_bfloat16* __restrict__ Ah,  const __nv_bfloat16* __restrict__ Al,
    const __nv_bfloat16* __restrict__ Bh,  const __nv_bfloat16* __restrict__ Bl,
    float* __restrict__ C, const float* __restrict__ bias,
    int M, int N, int K)
{
    __shared__ __align__(16) __nv_bfloat16 sAh[2][GBM*SAS], sAl[2][GBM*SAS];
    __shared__ __align__(16) __nv_bfloat16 sBh[2][GBN*SAS], sBl[2][GBN*SAS];

    const int mbase = blockIdx.y * GBM;
    const int nbase = blockIdx.x * GBN;

    const int tid = threadIdx.x;
    const int warp = tid >> 5, lane = tid & 31;
    const int wm  = (warp >> 2) * 32;
    const int wn  = (warp & 3) * 16;
    const int gid = lane >> 2, tig = lane & 3;
    const int lr  = tid >> 2;
    const int lc  = (tid & 3) * 8;

    const int nrow = nbase + lr;
    const int nr = (nrow < N) ? nrow : 0;

    float acc[2][2][4];
    #pragma unroll
    for (int a = 0; a < 2; a++)
        #pragma unroll
        for (int b = 0; b < 2; b++)
            #pragma unroll
            for (int c = 0; c < 4; c++) acc[a][b][c] = 0.f;

    const int niter = K / GBK;
    {
        cp16(&sAh[0][lr*SAS + lc], &Ah[(size_t)(mbase + lr) * K + lc]);
        cp16(&sAl[0][lr*SAS + lc], &Al[(size_t)(mbase + lr) * K + lc]);
        cp16(&sBh[0][lr*SAS + lc], &Bh[(size_t)nr * K + lc]);
        cp16(&sBl[0][lr*SAS + lc], &Bl[(size_t)nr * K + lc]);
        cp_commit();
    }

    for (int it = 0; it < niter; it++) {
        if (it + 1 < niter) {
            const int buf = (it + 1) & 1;
            const int gk = (it + 1) * GBK + lc;
            cp16(&sAh[buf][lr*SAS + lc], &Ah[(size_t)(mbase + lr) * K + gk]);
            cp16(&sAl[buf][lr*SAS + lc], &Al[(size_t)(mbase + lr) * K + gk]);
            cp16(&sBh[buf][lr*SAS + lc], &Bh[(size_t)nr * K + gk]);
            cp16(&sBl[buf][lr*SAS + lc], &Bl[(size_t)nr * K + gk]);
            cp_commit();
            cp_wait1();
        } else {
            cp_wait0();
        }
        __syncthreads();
        const int bf = it & 1;

        #pragma unroll
        for (int kk = 0; kk < GBK; kk += 16) {
            uint32_t ah[2][4], al[2][4];
            #pragma unroll
            for (int mi = 0; mi < 2; mi++) {
                const int r = wm + mi*16 + gid;
                const int c = kk + tig*2;
                ah[mi][0] = *(const uint32_t*)&sAh[bf][(r    )*SAS + c    ];
                ah[mi][1] = *(const uint32_t*)&sAh[bf][(r + 8)*SAS + c    ];
                ah[mi][2] = *(const uint32_t*)&sAh[bf][(r    )*SAS + c + 8];
                ah[mi][3] = *(const uint32_t*)&sAh[bf][(r + 8)*SAS + c + 8];
                al[mi][0] = *(const uint32_t*)&sAl[bf][(r    )*SAS + c    ];
                al[mi][1] = *(const uint32_t*)&sAl[bf][(r + 8)*SAS + c    ];
                al[mi][2] = *(const uint32_t*)&sAl[bf][(r    )*SAS + c + 8];
                al[mi][3] = *(const uint32_t*)&sAl[bf][(r + 8)*SAS + c + 8];
            }
            #pragma unroll
            for (int ni = 0; ni < 2; ni++) {
                const int n = wn + ni*8 + gid;
                const int c = kk + tig*2;
                const uint32_t b0h = *(const uint32_t*)&sBh[bf][n*SAS + c    ];
                const uint32_t b1h = *(const uint32_t*)&sBh[bf][n*SAS + c + 8];
                const uint32_t b0l = *(const uint32_t*)&sBl[bf][n*SAS + c    ];
                const uint32_t b1l = *(const uint32_t*)&sBl[bf][n*SAS + c + 8];
                #pragma unroll
                for (int mi = 0; mi < 2; mi++) {
                    mma16816(acc[mi][ni], ah[mi][0], ah[mi][1], ah[mi][2], ah[mi][3], b0h, b1h);
                    mma16816(acc[mi][ni], ah[mi][0], ah[mi][1], ah[mi][2], ah[mi][3], b0l, b1l);
                    mma16816(acc[mi][ni], al[mi][0], al[mi][1], al[mi][2], al[mi][3], b0h, b1h);
                }
            }
        }
        __syncthreads();
    }

    #pragma unroll
    for (int mi = 0; mi < 2; mi++) {
        #pragma unroll
        for (int ni = 0; ni < 2; ni++) {
            const int r = mbase + wm + mi*16 + gid;
            const int c = nbase + wn + ni*8 + tig*2;
            float b0 = 0.f, b1 = 0.f;
            if (bias != nullptr) {
                if (c     < N) b0 = bias[c];
                if (c + 1 < N) b1 = bias[c + 1];
            }
            if (c < N) {
                C[(size_t)(r    )*N + c] = acc[mi][ni][0] + b0;
                C[(size_t)(r + 8)*N + c] = acc[mi][ni][2] + b0;
            }
            if (c + 1 < N) {
                C[(size_t)(r    )*N + c + 1] = acc[mi][ni][1] + b1;
                C[(size_t)(r + 8)*N + c + 1] = acc[mi][ni][3] + b1;
            }
        }
    }
}

// ------------------------- fused attention -------------------------
__global__ void __launch_bounds__(512) attn_fused(const float* __restrict__ wscore)
{
    const int b = blockIdx.x;
    __shared__ __align__(16) __half2 s_hp2[HDIM/2];
    __shared__ __align__(16) float s_w[HDIM];
    __shared__ float s_e[NTIME];
    __shared__ float red[16];

    const int tid = threadIdx.x;
    const int warp = tid >> 5, lane = tid & 31;

    if (tid < 64)  ((uint4*)s_hp2)[tid] = ((const uint4*)(g_hp16 + b*HDIM))[tid];
    if (tid >= 128 && tid < 256) ((float4*)s_w)[tid - 128] = ((const float4*)wscore)[tid - 128];
    __syncthreads();

    uint4 hpv[2];
    float wv[16];
    #pragma unroll
    for (int jj = 0; jj < 2; jj++) {
        const int idx = lane + jj*32;
        hpv[jj] = ((const uint4*)s_hp2)[idx];
        #pragma unroll
        for (int q = 0; q < 8; q++) wv[jj*8 + q] = s_w[idx*8 + q];
    }

    #pragma unroll
    for (int it = 0; it < 16; it++) {
        const int t = warp + (it << 4);
        const uint4* row4 = (const uint4*)(g_fp16 + ((size_t)b * NTIME + t) * HDIM);
        float p = 0.f;
        #pragma unroll
        for (int jj = 0; jj < 2; jj++) {
            const uint4 v = row4[lane + jj*32];
            const __half2* vh = (const __half2*)&v;
            const __half2* hh = (const __half2*)&hpv[jj];
            #pragma unroll
            for (int q = 0; q < 4; q++) {
                float2 f = __half22float2(__hadd2(vh[q], hh[q]));
                p = fmaf(wv[jj*8 + 2*q],     tanh_ap(f.x), p);
                p = fmaf(wv[jj*8 + 2*q + 1], tanh_ap(f.y), p);
            }
        }
        p = warp_sum(p);
        if (lane == 0) s_e[t] = p;
    }
    __syncthreads();

    float v = (tid < NTIME) ? s_e[tid] : -1e30f;
    float m = warp_max(v);
    if (lane == 0) red[warp] = m;
    __syncthreads();
    if (warp == 0) {
        float x = (lane < 16) ? red[lane] : -1e30f;
        x = warp_max(x);
        if (lane == 0) red[0] = x;
    }
    __syncthreads();
    const float mx = red[0];
    __syncthreads();
    float ex = (tid < NTIME) ? __expf(v - mx) : 0.f;
    float s = warp_sum(ex);
    if (lane == 0) red[warp] = s;
    __syncthreads();
    if (warp == 0) {
        float x = (lane < 16) ? red[lane] : 0.f;
        x = warp_sum(x);
        if (lane == 0) red[0] = x;
    }
    __syncthreads();
    const float inv = 1.f / red[0];
    if (tid < NTIME) s_e[tid] = ex * inv;
    __syncthreads();

    float av[8];
    #pragma unroll
    for (int q = 0; q < 8; q++) av[q] = s_e[lane*8 + q];

    #pragma unroll
    for (int ic = 0; ic < 32; ic++) {
        const int c = warp + (ic << 4);
        const uint4 v4 = ((const uint4*)(g_f16ctx + ((size_t)b * NCH + c) * NTIME))[lane];
        const __half2* vh = (const __half2*)&v4;
        float p = 0.f;
        #pragma unroll
        for (int q = 0; q < 4; q++) {
            float2 f = __half22float2(vh[q]);
            p = fmaf(f.x, av[2*q],     p);
            p = fmaf(f.y, av[2*q + 1], p);
        }
        p = warp_sum(p);
        if (lane == 0) {
            __nv_bfloat16 h, l;
            split_val(p, h, l);
            g_ctx_h[b*NCH + c] = h;
            g_ctx_l[b*NCH + c] = l;
        }
    }
}

// ------------------------- fused gi/gh GEMM + GRU -------------------------
#define GGN 16
#define GRU_A_SZ (4*GBM*SAS)
#define GRU_B_SZ (12*GGN*SAS)
#define GRU_BUF (GRU_A_SZ + GRU_B_SZ)
#define GRU_SMEM_BYTES (2*GRU_BUF*2)

__global__ void __launch_bounds__(256) gemm_gru(
    const __nv_bfloat16* __restrict__ hin_h, const __nv_bfloat16* __restrict__ hin_l,
    const float* __restrict__ hin_f,
    __nv_bfloat16* __restrict__ hout_h, __nv_bfloat16* __restrict__ hout_l,
    float* __restrict__ hout_f,
    const float* __restrict__ bih, const float* __restrict__ bhh,
    int step)
{
    extern __shared__ __nv_bfloat16 dyn[];
    const int nbase = blockIdx.x * GGN;
    const int mbase = blockIdx.y * GBM;
    const int tid = threadIdx.x;
    const int warp = tid >> 5, lane = tid & 31;
    const int wm = (warp >> 1) * 16;
    const int wn = (warp & 1) * 8;
    const int gid = lane >> 2, tig = lane & 3;

    float acc[6][4];
    #pragma unroll
    for (int g = 0; g < 6; g++)
        #pragma unroll
        for (int i = 0; i < 4; i++) acc[g][i] = 0.f;

    const __nv_bfloat16* aptr[4] = { g_ctx_h, g_ctx_l, hin_h, hin_l };

    auto issue = [&](int kt, int buf) {
        __nv_bfloat16* base = dyn + buf * GRU_BUF;
        #pragma unroll
        for (int i = tid; i < 1792; i += 256) {
            const int chunk = i & 3;
            const int rowid = i >> 2;
            const __nv_bfloat16* src;
            __nv_bfloat16* dst;
            if (rowid < 256) {
                const int set = rowid >> 6, r = rowid & 63;
                src = aptr[set] + (size_t)(mbase + r) * HDIM + kt + chunk*8;
                dst = base + set*(GBM*SAS) + r*SAS + chunk*8;
            } else {
                const int rb = rowid - 256;
                const int set = rb >> 4, r = rb & 15;
                const int gate = set >> 1, hl = set & 1;
                const __nv_bfloat16* wsrc = (gate < 3) ? (hl ? g_Wih_l : g_Wih_h)
                                                       : (hl ? g_Whh_l : g_Whh_h);
                const int grow = ((gate < 3) ? gate : (gate - 3)) * HDIM + nbase + r;
                src = wsrc + (size_t)grow * HDIM + kt + chunk*8;
                dst = base + GRU_A_SZ + set*(GGN*SAS) + r*SAS + chunk*8;
            }
            cp16(dst, src);
        }
        cp_commit();
    };

    issue(0, 0);
    const int niter = HDIM / GBK;
    for (int it = 0; it < niter; it++) {
        if (it + 1 < niter) { issue((it + 1) * GBK, (it + 1) & 1); cp_wait1(); }
        else cp_wait0();
        __syncthreads();
        const __nv_bfloat16* base = dyn + (it & 1) * GRU_BUF;
        const __nv_bfloat16* sA0 = base;
        const __nv_bfloat16* sB0 = base + GRU_A_SZ;

        #pragma unroll
        for (int kk = 0; kk < GBK; kk += 16) {
            const int cc = kk + tig*2;
            const int r0 = wm + gid;
            uint32_t ac_h[4], ac_l[4], ah_h[4], ah_l[4];
            ac_h[0] = *(const uint32_t*)&sA0[0*(GBM*SAS) + (r0    )*SAS + cc    ];
            ac_h[1] = *(const uint32_t*)&sA0[0*(GBM*SAS) + (r0 + 8)*SAS + cc    ];
            ac_h[2] = *(const uint32_t*)&sA0[0*(GBM*SAS) + (r0    )*SAS + cc + 8];
            ac_h[3] = *(const uint32_t*)&sA0[0*(GBM*SAS) + (r0 + 8)*SAS + cc + 8];
            ac_l[0] = *(const uint32_t*)&sA0[1*(GBM*SAS) + (r0    )*SAS + cc    ];
            ac_l[1] = *(const uint32_t*)&sA0[1*(GBM*SAS) + (r0 + 8)*SAS + cc    ];
            ac_l[2] = *(const uint32_t*)&sA0[1*(GBM*SAS) + (r0    )*SAS + cc + 8];
            ac_l[3] = *(const uint32_t*)&sA0[1*(GBM*SAS) + (r0 + 8)*SAS + cc + 8];
            ah_h[0] = *(const uint32_t*)&sA0[2*(GBM*SAS) + (r0    )*SAS + cc    ];
            ah_h[1] = *(const uint32_t*)&sA0[2*(GBM*SAS) + (r0 + 8)*SAS + cc    ];
            ah_h[2] = *(const uint32_t*)&sA0[2*(GBM*SAS) + (r0    )*SAS + cc + 8];
            ah_h[3] = *(const uint32_t*)&sA0[2*(GBM*SAS) + (r0 + 8)*SAS + cc + 8];
            ah_l[0] = *(const uint32_t*)&sA0[3*(GBM*SAS) + (r0    )*SAS + cc    ];
            ah_l[1] = *(const uint32_t*)&sA0[3*(GBM*SAS) + (r0 + 8)*SAS + cc    ];
            ah_l[2] = *(const uint32_t*)&sA0[3*(GBM*SAS) + (r0    )*SAS + cc + 8];
            ah_l[3] = *(const uint32_t*)&sA0[3*(GBM*SAS) + (r0 + 8)*SAS + cc + 8];
            #pragma unroll
            for (int g = 0; g < 6; g++) {
                const int br = wn + gid;
                const uint32_t b0h = *(const uint32_t*)&sB0[(2*g  )*(GGN*SAS) + br*SAS + cc    ];
                const uint32_t b1h = *(const uint32_t*)&sB0[(2*g  )*(GGN*SAS) + br*SAS + cc + 8];
                const uint32_t b0l = *(const uint32_t*)&sB0[(2*g+1)*(GGN*SAS) + br*SAS + cc    ];
                const uint32_t b1l = *(const uint32_t*)&sB0[(2*g+1)*(GGN*SAS) + br*SAS + cc + 8];
                const uint32_t* Ah_ = (g < 3) ? ac_h : ah_h;
                const uint32_t* Al_ = (g < 3) ? ac_l : ah_l;
                mma16816(acc[g], Ah_[0], Ah_[1], Ah_[2], Ah_[3], b0h, b1h);
                mma16816(acc[g], Ah_[0], Ah_[1], Ah_[2], Ah_[3], b0l, b1l);
                mma16816(acc[g], Al_[0], Al_[1], Al_[2], Al_[3], b0h, b1h);
            }
        }
        __syncthreads();
    }

    const int row0 = mbase + wm + gid;
    const int j0 = nbase + wn + tig*2;
    #pragma unroll
    for (int mi = 0; mi < 2; mi++) {
        const int row = row0 + mi*8;
        #pragma unroll
        for (int ji = 0; ji < 2; ji++) {
            const int j = j0 + ji;
            const int ai = mi*2 + ji;
            const float ir  = acc[0][ai] + bih[j];
            const float iz  = acc[1][ai] + bih[HDIM + j];
            const float in_ = acc[2][ai] + bih[2*HDIM + j];
            const float hr  = acc[3][ai] + bhh[j];
            const float hz  = acc[4][ai] + bhh[HDIM + j];
            const float hn  = acc[5][ai] + bhh[2*HDIM + j];
            const float r = 1.f / (1.f + __expf(-(ir + hr)));
            const float z = 1.f / (1.f + __expf(-(iz + hz)));
            const float n = tanhf(in_ + r * hn);
            const float hprev = hin_f[row*HDIM + j];
            const float hnew = (1.f - z) * n + z * hprev;
            hout_f[row*HDIM + j] = hnew;
            g_h16[row*HDIM + j] = __float2half(hnew);
            __nv_bfloat16 hh, hl;
            split_val(hnew, hh, hl);
            hout_h[row*HDIM + j] = hh;
            hout_l[row*HDIM + j] = hl;
            const size_t o = ((size_t)(row*NSTEPS + step)) * HDIM + j;
            g_hid_h[o] = hh;
            g_hid_l[o] = hl;
        }
    }
}

// ------------------------- host -------------------------
template <typename T>
static T* sym(const void* s)
{
    void* p = nullptr;
    cudaGetSymbolAddress(&p, s);
    return (T*)p;
}

extern "C" void kernel_launch(void* const* d_in, const int* in_sizes, int n_in,
                              void* d_out, int out_size)
{
    const float* feats  = (const float*)d_in[0];
    const float* Wi2h   = (const float*)d_in[2];
    const float* Wh2h   = (const float*)d_in[3];
    const float* bh2h   = (const float*)d_in[4];
    const float* Wscore = (const float*)d_in[5];
    const float* Wih    = (const float*)d_in[6];
    const float* Whh    = (const float*)d_in[7];
    const float* bih    = (const float*)d_in[8];
    const float* bhh    = (const float*)d_in[9];
    const float* Wgen   = (const float*)d_in[10];
    const float* bgen   = (const float*)d_in[11];
    float* out = (float*)d_out;

    __half* A0f16   = sym<__half>(g_A0f16);
    __half* Wi2h16  = sym<__half>(g_Wi2h16);
    __half* Wh2h16  = sym<__half>(g_Wh2h16);
    __half* h16     = sym<__half>(g_h16);
    __half* fp16    = sym<__half>(g_fp16);
    __half* hp16    = sym<__half>(g_hp16);
    __nv_bfloat16* Wgen_h = sym<__nv_bfloat16>(g_Wgen_h);
    __nv_bfloat16* Wgen_l = sym<__nv_bfloat16>(g_Wgen_l);
    __nv_bfloat16* hidh   = sym<__nv_bfloat16>(g_hid_h);
    __nv_bfloat16* hidl   = sym<__nv_bfloat16>(g_hid_l);

    __nv_bfloat16* hbh[2] = { sym<__nv_bfloat16>(g_hA_h), sym<__nv_bfloat16>(g_hB_h) };
    __nv_bfloat16* hbl[2] = { sym<__nv_bfloat16>(g_hA_l), sym<__nv_bfloat16>(g_hB_l) };
    float*         hbf[2] = { sym<float>(g_hA_f), sym<float>(g_hB_f) };

    cudaFuncSetAttribute(gemm_gru, cudaFuncAttributeMaxDynamicSharedMemorySize, GRU_SMEM_BYTES);

    // ---- prologue ----
    {
        const int total = HDIM*NCH + HDIM*HDIM + 3*HDIM*NCH + 3*HDIM*HDIM + NOUT*HDIM;
        fused_split<<<(total + 255)/256, 256>>>(Wi2h, Wh2h, Wih, Whh, Wgen);
    }
    transpose_kernel<<<dim3(BT/32, NCH/32), dim3(32, 8)>>>(feats);
    feats16_zero_kernel<<<(int)(((size_t)NBAT*NCH*NTIME)/256), 256>>>(feats);

    // ---- GEMM0: feats_proj = feats^T @ Wi2h^T (fp16 single-pass) ----
    gemm_f16<<<dim3(HDIM/FBN, BT/FBM), 256>>>(
        A0f16, Wi2h16, fp16, nullptr, BT, HDIM, NCH);

    // ---- decode loop ----
    int cur = 0;
    for (int step = 0; step < NSTEPS; step++) {
        const int nxt = cur ^ 1;
        gemm_f16<<<dim3(HDIM/FBN, NBAT/FBM), 256>>>(
            h16, Wh2h16, hp16, bh2h, NBAT, HDIM, HDIM);
        attn_fused<<<NBAT, 512>>>(Wscore);
        gemm_gru<<<dim3(HDIM/GGN, NBAT/GBM), 256, GRU_SMEM_BYTES>>>(
            hbh[cur], hbl[cur], hbf[cur], hbh[nxt], hbl[nxt], hbf[nxt], bih, bhh, step);
        cur = nxt;
    }

    // ---- generator (bf16x3 for accuracy) ----
    gemm_x3<<<dim3((NOUT + GBN - 1)/GBN, (NBAT*NSTEPS)/GBM), 256>>>(
        hidh, hidl, Wgen_h, Wgen_l, out, bgen, NBAT*NSTEPS, NOUT, HDIM);
}